// round 9
// baseline (speedup 1.0000x reference)
#include <cuda_runtime.h>
#include <cuda_bf16.h>
#include <stdint.h>

#define TT    512
#define TOPK  2
#define NE    8
#define NH    2816
#define ND    1024
#define NPAIR 1024

// Scratch
__device__ int d_cnt[NE];
__device__ int d_slot[NE][NPAIR];
__device__ __align__(16) float          d_H1[(size_t)NPAIR * NH];
__device__ __align__(16) float          d_H3[(size_t)NPAIR * NH];
__device__ __align__(16) __nv_bfloat16  d_Ghi[(size_t)NPAIR * NH];
__device__ __align__(16) __nv_bfloat16  d_Glo[(size_t)NPAIR * NH];
__device__ __align__(16) __nv_bfloat16  d_xhi[TT * ND];
__device__ __align__(16) __nv_bfloat16  d_xlo[TT * ND];

// ---------------------------------------------------------------------------
__device__ __forceinline__ uint32_t smem_u32(const void* p) {
    uint32_t a;
    asm("{ .reg .u64 t; cvta.to.shared.u64 t, %1; cvt.u32.u64 %0, t; }" : "=r"(a) : "l"(p));
    return a;
}
__device__ __forceinline__ void ldsm4(uint32_t* r, uint32_t addr) {
    asm volatile("ldmatrix.sync.aligned.m8n8.x4.shared.b16 {%0,%1,%2,%3}, [%4];"
        : "=r"(r[0]), "=r"(r[1]), "=r"(r[2]), "=r"(r[3]) : "r"(addr));
}
__device__ __forceinline__ void mma16816(float* c, const uint32_t* a, const uint32_t* b) {
    asm volatile("mma.sync.aligned.m16n8k16.row.col.f32.bf16.bf16.f32 "
        "{%0,%1,%2,%3},{%4,%5,%6,%7},{%8,%9},{%0,%1,%2,%3};"
        : "+f"(c[0]), "+f"(c[1]), "+f"(c[2]), "+f"(c[3])
        : "r"(a[0]), "r"(a[1]), "r"(a[2]), "r"(a[3]), "r"(b[0]), "r"(b[1]));
}
__device__ __forceinline__ void cp16(uint32_t dst, const void* src) {
    asm volatile("cp.async.cg.shared.global [%0], [%1], 16;" :: "r"(dst), "l"(src) : "memory");
}
#define CP_COMMIT() asm volatile("cp.async.commit_group;" ::: "memory")
#define CP_WAIT0()  asm volatile("cp.async.wait_group 0;" ::: "memory")

__device__ __forceinline__ uint32_t pack2(__nv_bfloat16 e0, __nv_bfloat16 e1) {
    return (uint32_t)__bfloat16_as_ushort(e0) | ((uint32_t)__bfloat16_as_ushort(e1) << 16);
}
__device__ __forceinline__ void split_bf(float v, __nv_bfloat16& h, __nv_bfloat16& l) {
    h = __float2bfloat16(v);
    l = __float2bfloat16(v - __bfloat162float(h));
}

// ---------------------------------------------------------------------------
__global__ void route_kernel(const int* __restrict__ eidx) {
    __shared__ int s_cnt[NE];
    int tid = threadIdx.x;
    if (tid < NE) s_cnt[tid] = 0;
    __syncthreads();
    int e = eidx[tid];
    int slot = atomicAdd(&s_cnt[e], 1);
    d_slot[e][slot] = tid;
    __syncthreads();
    if (tid < NE) d_cnt[tid] = s_cnt[tid];
}

__global__ void dummy_kernel() {}

__global__ void prep_x(const float* __restrict__ x) {
    size_t i = ((size_t)blockIdx.x * blockDim.x + threadIdx.x) * 4;
    float4 v = *(const float4*)(x + i);
    __nv_bfloat16 h0, h1, h2, h3, l0, l1, l2, l3;
    split_bf(v.x, h0, l0); split_bf(v.y, h1, l1);
    split_bf(v.z, h2, l2); split_bf(v.w, h3, l3);
    *(uint2*)(d_xhi + i) = make_uint2(pack2(h0, h1), pack2(h2, h3));
    *(uint2*)(d_xlo + i) = make_uint2(pack2(l0, l1), pack2(l2, l3));
}

__global__ void gate_kernel() {
    size_t i = ((size_t)blockIdx.x * blockDim.x + threadIdx.x) * 4;
    float4 v1 = *(const float4*)(d_H1 + i);
    float4 v3 = *(const float4*)(d_H3 + i);
    float g0 = __fdividef(v1.x, 1.0f + __expf(-v1.x)) * v3.x;
    float g1 = __fdividef(v1.y, 1.0f + __expf(-v1.y)) * v3.y;
    float g2 = __fdividef(v1.z, 1.0f + __expf(-v1.z)) * v3.z;
    float g3 = __fdividef(v1.w, 1.0f + __expf(-v1.w)) * v3.w;
    __nv_bfloat16 h0, h1, h2, h3, l0, l1, l2, l3;
    split_bf(g0, h0, l0); split_bf(g1, h1, l1);
    split_bf(g2, h2, l2); split_bf(g3, h3, l3);
    *(uint2*)(d_Ghi + i) = make_uint2(pack2(h0, h1), pack2(h2, h3));
    *(uint2*)(d_Glo + i) = make_uint2(pack2(l0, l1), pack2(l2, l3));
}

// ---------------------------------------------------------------------------
// GEMM1: C[128 pairs x 128 h] = x_gathered . w{1|3}^T, K=1024 (16 chunks of 64)
// 512 threads, 4x4 warps (each 32x32). Double-buffered 64KB stages.
// MMA ordering is pass-major: 8 independent MMAs between accumulator reuses.
// ---------------------------------------------------------------------------
#define G1_STAGE 65536
#define G1_SMEM  (1024 + 2 * G1_STAGE)

__global__ __launch_bounds__(512) void gemm1_mma(
    const float* __restrict__ w1, const float* __restrict__ w3)
{
    int z = blockIdx.z, e = z >> 1, f = z & 1;
    int cnt = d_cnt[e];
    int trow0 = blockIdx.y * 128;
    if (trow0 >= cnt) return;
    int col0 = blockIdx.x * 128;
    const float* w = f ? w3 : w1;
    float* dH = f ? d_H3 : d_H1;

    extern __shared__ char smem[];
    int* s_p   = (int*)smem;
    int* s_tok = (int*)(smem + 512);
    uint32_t sb = smem_u32(smem);

    int tid = threadIdx.x, lane = tid & 31, wid = tid >> 5;
    if (tid < 128) {
        int r = trow0 + tid;
        int p = (r < cnt) ? d_slot[e][r] : d_slot[e][0];
        s_p[tid] = p; s_tok[tid] = p >> 1;
    }
    __syncthreads();

    int arow = tid >> 2, aq = tid & 3;
    uint32_t aswz = (uint32_t)((arow & 7) << 4);
    const __nv_bfloat16* xh = d_xhi + (size_t)s_tok[arow] * ND + aq * 16;
    const __nv_bfloat16* xl = d_xlo + (size_t)s_tok[arow] * ND + aq * 16;
    uint32_t aoff[2];
    #pragma unroll
    for (int j = 0; j < 2; j++)
        aoff[j] = (uint32_t)arow * 128 + (((uint32_t)(aq * 32 + j * 16)) ^ aswz);

    const float* wrow = w + ((size_t)e * NH + col0 + arow) * ND + aq * 16;
    uint32_t boff[4];
    #pragma unroll
    for (int j = 0; j < 4; j++)
        boff[j] = (uint32_t)arow * 128 + (((uint32_t)(aq * 32 + j * 8)) ^ aswz);

    float acc[2][4][4];
    #pragma unroll
    for (int a = 0; a < 2; a++)
        #pragma unroll
        for (int b = 0; b < 4; b++)
            #pragma unroll
            for (int c = 0; c < 4; c++) acc[a][b][c] = 0.0f;

    int wm = wid & 3, wn = wid >> 2;

    float4 rb[4];
    {
        uint32_t base = sb + 1024;
        #pragma unroll
        for (int j = 0; j < 2; j++) {
            cp16(base + aoff[j], (const char*)xh + j * 16);
            cp16(base + 16384 + aoff[j], (const char*)xl + j * 16);
        }
        CP_COMMIT();
        #pragma unroll
        for (int j = 0; j < 4; j++) rb[j] = *(const float4*)(wrow + 4 * j);
    }

    #pragma unroll 1
    for (int kc = 0; kc < 16; kc++) {
        int s = kc & 1;
        char* stage = smem + 1024 + s * G1_STAGE;
        #pragma unroll
        for (int j = 0; j < 4; j++) {
            float4 v = rb[j];
            __nv_bfloat16 h0, h1, h2, h3, l0, l1, l2, l3;
            split_bf(v.x, h0, l0); split_bf(v.y, h1, l1);
            split_bf(v.z, h2, l2); split_bf(v.w, h3, l3);
            *(uint32_t*)(stage + 32768 + boff[j])     = pack2(h0, h1);
            *(uint32_t*)(stage + 32768 + boff[j] + 4) = pack2(h2, h3);
            *(uint32_t*)(stage + 49152 + boff[j])     = pack2(l0, l1);
            *(uint32_t*)(stage + 49152 + boff[j] + 4) = pack2(l2, l3);
        }
        CP_WAIT0();
        __syncthreads();
        if (kc < 15) {
            uint32_t base = sb + 1024 + (s ^ 1) * G1_STAGE;
            const char* srcH = (const char*)(xh + (kc + 1) * 64);
            const char* srcL = (const char*)(xl + (kc + 1) * 64);
            #pragma unroll
            for (int j = 0; j < 2; j++) {
                cp16(base + aoff[j], srcH + j * 16);
                cp16(base + 16384 + aoff[j], srcL + j * 16);
            }
            CP_COMMIT();
            #pragma unroll
            for (int j = 0; j < 4; j++)
                rb[j] = *(const float4*)(wrow + (kc + 1) * 64 + 4 * j);
        }
        uint32_t uAH = sb + 1024 + s * G1_STAGE;
        uint32_t uAL = uAH + 16384;
        uint32_t uBH = uAH + 32768;
        uint32_t uBL = uAH + 49152;
        #pragma unroll
        for (int ks = 0; ks < 4; ks++) {
            uint32_t Ah[2][4], Al[2][4], Bh[2][4], Bl[2][4];
            int kb = ks * 32;
            #pragma unroll
            for (int mi = 0; mi < 2; mi++) {
                int row = wm * 32 + mi * 16 + (lane & 15);
                uint32_t b = (uint32_t)(kb + ((lane >> 4) << 4));
                uint32_t off = (uint32_t)row * 128 + (b ^ (uint32_t)((row & 7) << 4));
                ldsm4(Ah[mi], uAH + off);
                ldsm4(Al[mi], uAL + off);
            }
            #pragma unroll
            for (int nb = 0; nb < 2; nb++) {
                int row = wn * 32 + nb * 16 + (lane & 7) + (((lane >> 4) & 1) << 3);
                uint32_t b = (uint32_t)(kb + (((lane >> 3) & 1) << 4));
                uint32_t off = (uint32_t)row * 128 + (b ^ (uint32_t)((row & 7) << 4));
                ldsm4(Bh[nb], uBH + off);
                ldsm4(Bl[nb], uBL + off);
            }
            // pass-major: 8 independent MMAs between reuses of any accumulator
            #pragma unroll
            for (int pass = 0; pass < 3; pass++) {
                #pragma unroll
                for (int mi = 0; mi < 2; mi++)
                    #pragma unroll
                    for (int nb = 0; nb < 2; nb++) {
                        const uint32_t* a  = (pass == 2) ? Al[mi] : Ah[mi];
                        const uint32_t* b0 = (pass == 1) ? &Bl[nb][0] : &Bh[nb][0];
                        const uint32_t* b2 = (pass == 1) ? &Bl[nb][2] : &Bh[nb][2];
                        mma16816(acc[mi][2 * nb],     a, b0);
                        mma16816(acc[mi][2 * nb + 1], a, b2);
                    }
            }
        }
    }

    int cntLoc = cnt - trow0; if (cntLoc > 128) cntLoc = 128;
    #pragma unroll
    for (int mi = 0; mi < 2; mi++) {
        int r0 = wm * 32 + mi * 16 + (lane >> 2);
        int r1 = r0 + 8;
        #pragma unroll
        for (int ni = 0; ni < 4; ni++) {
            int col = col0 + wn * 32 + ni * 8 + (lane & 3) * 2;
            if (r0 < cntLoc)
                *(float2*)&dH[(size_t)s_p[r0] * NH + col] =
                    make_float2(acc[mi][ni][0], acc[mi][ni][1]);
            if (r1 < cntLoc)
                *(float2*)&dH[(size_t)s_p[r1] * NH + col] =
                    make_float2(acc[mi][ni][2], acc[mi][ni][3]);
        }
    }
}

// ---------------------------------------------------------------------------
// GEMM2: C[128 pairs x 64 d] = G . w2, K=2816 (44 chunks of 64)
// 512 threads, 4x4 warps (each 32x16). Pass-major MMA ordering.
// ---------------------------------------------------------------------------
#define G2_STAGE 49152
#define G2_SMEM  (512 + 2 * G2_STAGE)

__global__ __launch_bounds__(512) void gemm2_mma(
    const float* __restrict__ w2, float* __restrict__ out)
{
    int e = blockIdx.z;
    int cnt = d_cnt[e];
    int trow0 = blockIdx.y * 128;
    if (trow0 >= cnt) return;
    int col0 = blockIdx.x * 64;

    extern __shared__ char smem[];
    int* s_p = (int*)smem;
    uint32_t sb = smem_u32(smem);

    int tid = threadIdx.x, lane = tid & 31, wid = tid >> 5;
    if (tid < 128) {
        int r = trow0 + tid;
        s_p[tid] = (r < cnt) ? d_slot[e][r] : d_slot[e][0];
    }
    __syncthreads();

    int arow = tid >> 2, aq = tid & 3;
    uint32_t aswz = (uint32_t)((arow & 7) << 4);
    const __nv_bfloat16* gh = d_Ghi + (size_t)s_p[arow] * NH + aq * 16;
    const __nv_bfloat16* gl = d_Glo + (size_t)s_p[arow] * NH + aq * 16;
    uint32_t aoff[2];
    #pragma unroll
    for (int j = 0; j < 2; j++)
        aoff[j] = (uint32_t)arow * 128 + (((uint32_t)(aq * 32 + j * 16)) ^ aswz);

    int h = (tid & 31) * 2;
    int d0 = (tid >> 5) * 4;
    const float* bp = w2 + ((size_t)e * NH + h) * ND + col0 + d0;
    uint32_t bboff[4];
    #pragma unroll
    for (int m = 0; m < 4; m++) {
        int d = d0 + m;
        bboff[m] = (uint32_t)d * 128 + (((uint32_t)(h * 2)) ^ (uint32_t)((d & 7) << 4));
    }

    float acc[2][2][4];
    #pragma unroll
    for (int a = 0; a < 2; a++)
        #pragma unroll
        for (int b = 0; b < 2; b++)
            #pragma unroll
            for (int c = 0; c < 4; c++) acc[a][b][c] = 0.0f;

    int wm = wid & 3, wn = wid >> 2;

    float4 rb0, rb1;
    {
        uint32_t base = sb + 512;
        #pragma unroll
        for (int j = 0; j < 2; j++) {
            cp16(base + aoff[j], (const char*)gh + j * 16);
            cp16(base + 16384 + aoff[j], (const char*)gl + j * 16);
        }
        CP_COMMIT();
        rb0 = *(const float4*)bp;
        rb1 = *(const float4*)(bp + ND);
    }

    #pragma unroll 1
    for (int kc = 0; kc < 44; kc++) {
        int s = kc & 1;
        char* stage = smem + 512 + s * G2_STAGE;
        {
            float va[4] = { rb0.x, rb0.y, rb0.z, rb0.w };
            float vb[4] = { rb1.x, rb1.y, rb1.z, rb1.w };
            #pragma unroll
            for (int m = 0; m < 4; m++) {
                __nv_bfloat16 ha, la, hb, lb;
                split_bf(va[m], ha, la);
                split_bf(vb[m], hb, lb);
                *(uint32_t*)(stage + 32768 + bboff[m]) = pack2(ha, hb);
                *(uint32_t*)(stage + 40960 + bboff[m]) = pack2(la, lb);
            }
        }
        CP_WAIT0();
        __syncthreads();
        if (kc < 43) {
            uint32_t base = sb + 512 + (s ^ 1) * G2_STAGE;
            const char* srcH = (const char*)(gh + (kc + 1) * 64);
            const char* srcL = (const char*)(gl + (kc + 1) * 64);
            #pragma unroll
            for (int j = 0; j < 2; j++) {
                cp16(base + aoff[j], srcH + j * 16);
                cp16(base + 16384 + aoff[j], srcL + j * 16);
            }
            CP_COMMIT();
            const float* bpn = bp + (size_t)(kc + 1) * 64 * ND;
            rb0 = *(const float4*)bpn;
            rb1 = *(const float4*)(bpn + ND);
        }
        uint32_t uAH = sb + 512 + s * G2_STAGE;
        uint32_t uAL = uAH + 16384;
        uint32_t uBH = uAH + 32768;
        uint32_t uBL = uAH + 40960;
        #pragma unroll
        for (int ks = 0; ks < 4; ks++) {
            uint32_t Ah[2][4], Al[2][4], Bh[4], Bl[4];
            int kb = ks * 32;
            #pragma unroll
            for (int mi = 0; mi < 2; mi++) {
                int row = wm * 32 + mi * 16 + (lane & 15);
                uint32_t b = (uint32_t)(kb + ((lane >> 4) << 4));
                uint32_t off = (uint32_t)row * 128 + (b ^ (uint32_t)((row & 7) << 4));
                ldsm4(Ah[mi], uAH + off);
                ldsm4(Al[mi], uAL + off);
            }
            {
                int row = wn * 16 + (lane & 7) + (((lane >> 4) & 1) << 3);
                uint32_t b = (uint32_t)(kb + (((lane >> 3) & 1) << 4));
                uint32_t off = (uint32_t)row * 128 + (b ^ (uint32_t)((row & 7) << 4));
                ldsm4(Bh, uBH + off);
                ldsm4(Bl, uBL + off);
            }
            // pass-major: 4 independent MMAs between accumulator reuses
            #pragma unroll
            for (int pass = 0; pass < 3; pass++) {
                #pragma unroll
                for (int mi = 0; mi < 2; mi++) {
                    const uint32_t* a  = (pass == 2) ? Al[mi] : Ah[mi];
                    const uint32_t* b0 = (pass == 1) ? &Bl[0] : &Bh[0];
                    const uint32_t* b2 = (pass == 1) ? &Bl[2] : &Bh[2];
                    mma16816(acc[mi][0], a, b0);
                    mma16816(acc[mi][1], a, b2);
                }
            }
        }
    }

    int cntLoc = cnt - trow0; if (cntLoc > 128) cntLoc = 128;
    #pragma unroll
    for (int mi = 0; mi < 2; mi++) {
        int r0 = wm * 32 + mi * 16 + (lane >> 2);
        int r1 = r0 + 8;
        #pragma unroll
        for (int ni = 0; ni < 2; ni++) {
            int col = col0 + wn * 16 + ni * 8 + (lane & 3) * 2;
            if (r0 < cntLoc)
                *(float2*)&out[(size_t)s_p[r0] * ND + col] =
                    make_float2(acc[mi][ni][0], acc[mi][ni][1]);
            if (r1 < cntLoc)
                *(float2*)&out[(size_t)s_p[r1] * ND + col] =
                    make_float2(acc[mi][ni][2], acc[mi][ni][3]);
        }
    }
}

// ---------------------------------------------------------------------------
extern "C" void kernel_launch(void* const* d_in, const int* in_sizes, int n_in,
                              void* d_out, int out_size) {
    const float* x    = (const float*)d_in[0];
    const int*   eidx = (const int*)d_in[1];   // int32 (JAX default int)
    const float* w1   = (const float*)d_in[2];
    const float* w2   = (const float*)d_in[3];
    const float* w3   = (const float*)d_in[4];
    float*       out  = (float*)d_out;

    static bool attr_done = false;
    if (!attr_done) {
        cudaFuncSetAttribute(gemm1_mma, cudaFuncAttributeMaxDynamicSharedMemorySize, G1_SMEM);
        cudaFuncSetAttribute(gemm2_mma, cudaFuncAttributeMaxDynamicSharedMemorySize, G2_SMEM);
        attr_done = true;
    }

    route_kernel<<<1, NPAIR>>>(eidx);
    prep_x<<<(TT * ND / 4) / 256, 256>>>(x);
    dummy_kernel<<<1, 32>>>();   // keeps ncu's profiled slot on gemm1

    dim3 g1(NH / 128, NPAIR / 128, NE * 2);   // 22 x 8 x 16
    gemm1_mma<<<g1, 512, G1_SMEM>>>(w1, w3);

    gate_kernel<<<(int)(((size_t)NPAIR * NH / 4) / 256), 256>>>();

    dim3 g2(ND / 64, NPAIR / 128, NE);        // 16 x 8 x 8
    gemm2_mma<<<g2, 512, G2_SMEM>>>(w2, out);
}

// round 10
// speedup vs baseline: 1.5075x; 1.5075x over previous
#include <cuda_runtime.h>
#include <cuda_fp16.h>
#include <stdint.h>

#define TT    512
#define TOPK  2
#define NE    8
#define NH    2816
#define ND    1024
#define NPAIR 1024

// Scratch
__device__ int d_cnt[NE];
__device__ int d_slot[NE][NPAIR];
__device__ __align__(16) float  d_H1[(size_t)NPAIR * NH];
__device__ __align__(16) float  d_H3[(size_t)NPAIR * NH];
__device__ __align__(16) __half d_Gh[(size_t)NPAIR * NH];
__device__ __align__(16) __half d_xh[TT * ND];

// ---------------------------------------------------------------------------
__device__ __forceinline__ uint32_t smem_u32(const void* p) {
    uint32_t a;
    asm("{ .reg .u64 t; cvta.to.shared.u64 t, %1; cvt.u32.u64 %0, t; }" : "=r"(a) : "l"(p));
    return a;
}
__device__ __forceinline__ void ldsm4(uint32_t* r, uint32_t addr) {
    asm volatile("ldmatrix.sync.aligned.m8n8.x4.shared.b16 {%0,%1,%2,%3}, [%4];"
        : "=r"(r[0]), "=r"(r[1]), "=r"(r[2]), "=r"(r[3]) : "r"(addr));
}
__device__ __forceinline__ void mma16816h(float* c, const uint32_t* a, const uint32_t* b) {
    asm volatile("mma.sync.aligned.m16n8k16.row.col.f32.f16.f16.f32 "
        "{%0,%1,%2,%3},{%4,%5,%6,%7},{%8,%9},{%0,%1,%2,%3};"
        : "+f"(c[0]), "+f"(c[1]), "+f"(c[2]), "+f"(c[3])
        : "r"(a[0]), "r"(a[1]), "r"(a[2]), "r"(a[3]), "r"(b[0]), "r"(b[1]));
}
__device__ __forceinline__ void cp16(uint32_t dst, const void* src) {
    asm volatile("cp.async.cg.shared.global [%0], [%1], 16;" :: "r"(dst), "l"(src) : "memory");
}
#define CP_COMMIT() asm volatile("cp.async.commit_group;" ::: "memory")
#define CP_WAIT0()  asm volatile("cp.async.wait_group 0;" ::: "memory")

__device__ __forceinline__ uint32_t pack2h(__half e0, __half e1) {
    return (uint32_t)__half_as_ushort(e0) | ((uint32_t)__half_as_ushort(e1) << 16);
}

// ---------------------------------------------------------------------------
__global__ void route_kernel(const int* __restrict__ eidx) {
    __shared__ int s_cnt[NE];
    int tid = threadIdx.x;
    if (tid < NE) s_cnt[tid] = 0;
    __syncthreads();
    int e = eidx[tid];
    int slot = atomicAdd(&s_cnt[e], 1);
    d_slot[e][slot] = tid;
    __syncthreads();
    if (tid < NE) d_cnt[tid] = s_cnt[tid];
}

__global__ void dummy_kernel() {}

__global__ void prep_x(const float* __restrict__ x) {
    size_t i = ((size_t)blockIdx.x * blockDim.x + threadIdx.x) * 4;
    float4 v = *(const float4*)(x + i);
    uint2 hv = make_uint2(pack2h(__float2half_rn(v.x), __float2half_rn(v.y)),
                          pack2h(__float2half_rn(v.z), __float2half_rn(v.w)));
    *(uint2*)(d_xh + i) = hv;
}

__global__ void gate_kernel() {
    size_t i = ((size_t)blockIdx.x * blockDim.x + threadIdx.x) * 4;
    float4 v1 = *(const float4*)(d_H1 + i);
    float4 v3 = *(const float4*)(d_H3 + i);
    float g0 = __fdividef(v1.x, 1.0f + __expf(-v1.x)) * v3.x;
    float g1 = __fdividef(v1.y, 1.0f + __expf(-v1.y)) * v3.y;
    float g2 = __fdividef(v1.z, 1.0f + __expf(-v1.z)) * v3.z;
    float g3 = __fdividef(v1.w, 1.0f + __expf(-v1.w)) * v3.w;
    *(uint2*)(d_Gh + i) = make_uint2(pack2h(__float2half_rn(g0), __float2half_rn(g1)),
                                     pack2h(__float2half_rn(g2), __float2half_rn(g3)));
}

// ---------------------------------------------------------------------------
// GEMM1: C[128 pairs x 128 h] = x_gathered . w{1|3}^T, K=1024 (16 chunks of 64)
// Single-pass fp16. 512 threads, 4x4 warps (each 32x32).
// Double-buffered 32KB stages: AH(16K) BH(16K).
// Weight LDG prefetch distance 2 (ping-pong rb[2]).
// ---------------------------------------------------------------------------
#define G1_STAGE 32768
#define G1_SMEM  (1024 + 2 * G1_STAGE)

__global__ __launch_bounds__(512) void gemm1_mma(
    const float* __restrict__ w1, const float* __restrict__ w3)
{
    int z = blockIdx.z, e = z >> 1, f = z & 1;
    int cnt = d_cnt[e];
    int trow0 = blockIdx.y * 128;
    if (trow0 >= cnt) return;
    int col0 = blockIdx.x * 128;
    const float* w = f ? w3 : w1;
    float* dH = f ? d_H3 : d_H1;

    extern __shared__ char smem[];
    int* s_p   = (int*)smem;
    int* s_tok = (int*)(smem + 512);
    uint32_t sb = smem_u32(smem);

    int tid = threadIdx.x, lane = tid & 31, wid = tid >> 5;
    if (tid < 128) {
        int r = trow0 + tid;
        int p = (r < cnt) ? d_slot[e][r] : d_slot[e][0];
        s_p[tid] = p; s_tok[tid] = p >> 1;
    }
    __syncthreads();

    int arow = tid >> 2, aq = tid & 3;
    uint32_t aswz = (uint32_t)((arow & 7) << 4);
    const __half* xh = d_xh + (size_t)s_tok[arow] * ND + aq * 16;
    uint32_t aoff[2];
    #pragma unroll
    for (int j = 0; j < 2; j++)
        aoff[j] = (uint32_t)arow * 128 + (((uint32_t)(aq * 32 + j * 16)) ^ aswz);

    const float* wrow = w + ((size_t)e * NH + col0 + arow) * ND + aq * 16;
    uint32_t boff[4];
    #pragma unroll
    for (int j = 0; j < 4; j++)
        boff[j] = (uint32_t)arow * 128 + (((uint32_t)(aq * 32 + j * 8)) ^ aswz);

    float acc[2][4][4];
    #pragma unroll
    for (int a = 0; a < 2; a++)
        #pragma unroll
        for (int b = 0; b < 4; b++)
            #pragma unroll
            for (int c = 0; c < 4; c++) acc[a][b][c] = 0.0f;

    int wm = wid & 3, wn = wid >> 2;

    // prologue: weights for chunks 0 and 1; A chunk 0 via cp.async
    float4 rb[2][4];
    {
        uint32_t base = sb + 1024;
        #pragma unroll
        for (int j = 0; j < 2; j++)
            cp16(base + aoff[j], (const char*)xh + j * 16);
        CP_COMMIT();
        #pragma unroll
        for (int j = 0; j < 4; j++) {
            rb[0][j] = *(const float4*)(wrow + 4 * j);
            rb[1][j] = *(const float4*)(wrow + 64 + 4 * j);
        }
    }

    #pragma unroll 2
    for (int kc = 0; kc < 16; kc++) {
        int s = kc & 1;
        char* stage = smem + 1024 + s * G1_STAGE;
        // store B(kc) from rb[kc&1]
        #pragma unroll
        for (int j = 0; j < 4; j++) {
            float4 v = rb[s][j];
            *(uint32_t*)(stage + 16384 + boff[j]) =
                pack2h(__float2half_rn(v.x), __float2half_rn(v.y));
            *(uint32_t*)(stage + 16384 + boff[j] + 4) =
                pack2h(__float2half_rn(v.z), __float2half_rn(v.w));
        }
        CP_WAIT0();
        __syncthreads();
        if (kc < 15) {
            uint32_t base = sb + 1024 + (s ^ 1) * G1_STAGE;
            const char* srcH = (const char*)(xh + (kc + 1) * 64);
            #pragma unroll
            for (int j = 0; j < 2; j++)
                cp16(base + aoff[j], srcH + j * 16);
            CP_COMMIT();
        }
        if (kc < 14) {
            // weights for chunk kc+2 into the buffer just consumed
            #pragma unroll
            for (int j = 0; j < 4; j++)
                rb[s][j] = *(const float4*)(wrow + (kc + 2) * 64 + 4 * j);
        }
        // MMA on stage s
        uint32_t uAH = sb + 1024 + s * G1_STAGE;
        uint32_t uBH = uAH + 16384;
        #pragma unroll
        for (int ks = 0; ks < 4; ks++) {
            uint32_t Ah[2][4], Bh[2][4];
            int kb = ks * 32;
            #pragma unroll
            for (int mi = 0; mi < 2; mi++) {
                int row = wm * 32 + mi * 16 + (lane & 15);
                uint32_t b = (uint32_t)(kb + ((lane >> 4) << 4));
                uint32_t off = (uint32_t)row * 128 + (b ^ (uint32_t)((row & 7) << 4));
                ldsm4(Ah[mi], uAH + off);
            }
            #pragma unroll
            for (int nb = 0; nb < 2; nb++) {
                int row = wn * 32 + nb * 16 + (lane & 7) + (((lane >> 4) & 1) << 3);
                uint32_t b = (uint32_t)(kb + (((lane >> 3) & 1) << 4));
                uint32_t off = (uint32_t)row * 128 + (b ^ (uint32_t)((row & 7) << 4));
                ldsm4(Bh[nb], uBH + off);
            }
            #pragma unroll
            for (int mi = 0; mi < 2; mi++)
                #pragma unroll
                for (int nb = 0; nb < 2; nb++) {
                    mma16816h(acc[mi][2 * nb],     Ah[mi], &Bh[nb][0]);
                    mma16816h(acc[mi][2 * nb + 1], Ah[mi], &Bh[nb][2]);
                }
        }
    }

    int cntLoc = cnt - trow0; if (cntLoc > 128) cntLoc = 128;
    #pragma unroll
    for (int mi = 0; mi < 2; mi++) {
        int r0 = wm * 32 + mi * 16 + (lane >> 2);
        int r1 = r0 + 8;
        #pragma unroll
        for (int ni = 0; ni < 4; ni++) {
            int col = col0 + wn * 32 + ni * 8 + (lane & 3) * 2;
            if (r0 < cntLoc)
                *(float2*)&dH[(size_t)s_p[r0] * NH + col] =
                    make_float2(acc[mi][ni][0], acc[mi][ni][1]);
            if (r1 < cntLoc)
                *(float2*)&dH[(size_t)s_p[r1] * NH + col] =
                    make_float2(acc[mi][ni][2], acc[mi][ni][3]);
        }
    }
}

// ---------------------------------------------------------------------------
// GEMM2: C[128 pairs x 64 d] = G . w2, K=2816 (44 chunks of 64)
// Single-pass fp16. 512 threads, 4x4 warps (each 32x16).
// Double-buffered 24KB stages: AH(16K) BH(8K). Weight prefetch distance 2.
// ---------------------------------------------------------------------------
#define G2_STAGE 24576
#define G2_SMEM  (512 + 2 * G2_STAGE)

__global__ __launch_bounds__(512) void gemm2_mma(
    const float* __restrict__ w2, float* __restrict__ out)
{
    int e = blockIdx.z;
    int cnt = d_cnt[e];
    int trow0 = blockIdx.y * 128;
    if (trow0 >= cnt) return;
    int col0 = blockIdx.x * 64;

    extern __shared__ char smem[];
    int* s_p = (int*)smem;
    uint32_t sb = smem_u32(smem);

    int tid = threadIdx.x, lane = tid & 31, wid = tid >> 5;
    if (tid < 128) {
        int r = trow0 + tid;
        s_p[tid] = (r < cnt) ? d_slot[e][r] : d_slot[e][0];
    }
    __syncthreads();

    int arow = tid >> 2, aq = tid & 3;
    uint32_t aswz = (uint32_t)((arow & 7) << 4);
    const __half* gh = d_Gh + (size_t)s_p[arow] * NH + aq * 16;
    uint32_t aoff[2];
    #pragma unroll
    for (int j = 0; j < 2; j++)
        aoff[j] = (uint32_t)arow * 128 + (((uint32_t)(aq * 32 + j * 16)) ^ aswz);

    int h = (tid & 31) * 2;
    int d0 = (tid >> 5) * 4;
    const float* bp = w2 + ((size_t)e * NH + h) * ND + col0 + d0;
    uint32_t bboff[4];
    #pragma unroll
    for (int m = 0; m < 4; m++) {
        int d = d0 + m;
        bboff[m] = (uint32_t)d * 128 + (((uint32_t)(h * 2)) ^ (uint32_t)((d & 7) << 4));
    }

    float acc[2][2][4];
    #pragma unroll
    for (int a = 0; a < 2; a++)
        #pragma unroll
        for (int b = 0; b < 2; b++)
            #pragma unroll
            for (int c = 0; c < 4; c++) acc[a][b][c] = 0.0f;

    int wm = wid & 3, wn = wid >> 2;

    // prologue: weights chunks 0,1; A chunk 0
    float4 r0b[2], r1b[2];   // [buf] rows h and h+1
    {
        uint32_t base = sb + 512;
        #pragma unroll
        for (int j = 0; j < 2; j++)
            cp16(base + aoff[j], (const char*)gh + j * 16);
        CP_COMMIT();
        r0b[0] = *(const float4*)bp;
        r1b[0] = *(const float4*)(bp + ND);
        const float* bp1 = bp + (size_t)64 * ND;
        r0b[1] = *(const float4*)bp1;
        r1b[1] = *(const float4*)(bp1 + ND);
    }

    #pragma unroll 2
    for (int kc = 0; kc < 44; kc++) {
        int s = kc & 1;
        char* stage = smem + 512 + s * G2_STAGE;
        {
            float va[4] = { r0b[s].x, r0b[s].y, r0b[s].z, r0b[s].w };
            float vb[4] = { r1b[s].x, r1b[s].y, r1b[s].z, r1b[s].w };
            #pragma unroll
            for (int m = 0; m < 4; m++)
                *(uint32_t*)(stage + 16384 + bboff[m]) =
                    pack2h(__float2half_rn(va[m]), __float2half_rn(vb[m]));
        }
        CP_WAIT0();
        __syncthreads();
        if (kc < 43) {
            uint32_t base = sb + 512 + (s ^ 1) * G2_STAGE;
            const char* srcH = (const char*)(gh + (kc + 1) * 64);
            #pragma unroll
            for (int j = 0; j < 2; j++)
                cp16(base + aoff[j], srcH + j * 16);
            CP_COMMIT();
        }
        if (kc < 42) {
            const float* bpn = bp + (size_t)(kc + 2) * 64 * ND;
            r0b[s] = *(const float4*)bpn;
            r1b[s] = *(const float4*)(bpn + ND);
        }
        uint32_t uAH = sb + 512 + s * G2_STAGE;
        uint32_t uBH = uAH + 16384;
        #pragma unroll
        for (int ks = 0; ks < 4; ks++) {
            uint32_t Ah[2][4], Bh[4];
            int kb = ks * 32;
            #pragma unroll
            for (int mi = 0; mi < 2; mi++) {
                int row = wm * 32 + mi * 16 + (lane & 15);
                uint32_t b = (uint32_t)(kb + ((lane >> 4) << 4));
                uint32_t off = (uint32_t)row * 128 + (b ^ (uint32_t)((row & 7) << 4));
                ldsm4(Ah[mi], uAH + off);
            }
            {
                int row = wn * 16 + (lane & 7) + (((lane >> 4) & 1) << 3);
                uint32_t b = (uint32_t)(kb + (((lane >> 3) & 1) << 4));
                uint32_t off = (uint32_t)row * 128 + (b ^ (uint32_t)((row & 7) << 4));
                ldsm4(Bh, uBH + off);
            }
            #pragma unroll
            for (int mi = 0; mi < 2; mi++) {
                mma16816h(acc[mi][0], Ah[mi], &Bh[0]);
                mma16816h(acc[mi][1], Ah[mi], &Bh[2]);
            }
        }
    }

    int cntLoc = cnt - trow0; if (cntLoc > 128) cntLoc = 128;
    #pragma unroll
    for (int mi = 0; mi < 2; mi++) {
        int r0 = wm * 32 + mi * 16 + (lane >> 2);
        int r1 = r0 + 8;
        #pragma unroll
        for (int ni = 0; ni < 2; ni++) {
            int col = col0 + wn * 16 + ni * 8 + (lane & 3) * 2;
            if (r0 < cntLoc)
                *(float2*)&out[(size_t)s_p[r0] * ND + col] =
                    make_float2(acc[mi][ni][0], acc[mi][ni][1]);
            if (r1 < cntLoc)
                *(float2*)&out[(size_t)s_p[r1] * ND + col] =
                    make_float2(acc[mi][ni][2], acc[mi][ni][3]);
        }
    }
}

// ---------------------------------------------------------------------------
extern "C" void kernel_launch(void* const* d_in, const int* in_sizes, int n_in,
                              void* d_out, int out_size) {
    const float* x    = (const float*)d_in[0];
    const int*   eidx = (const int*)d_in[1];   // int32 (JAX default int)
    const float* w1   = (const float*)d_in[2];
    const float* w2   = (const float*)d_in[3];
    const float* w3   = (const float*)d_in[4];
    float*       out  = (float*)d_out;

    static bool attr_done = false;
    if (!attr_done) {
        cudaFuncSetAttribute(gemm1_mma, cudaFuncAttributeMaxDynamicSharedMemorySize, G1_SMEM);
        cudaFuncSetAttribute(gemm2_mma, cudaFuncAttributeMaxDynamicSharedMemorySize, G2_SMEM);
        attr_done = true;
    }

    route_kernel<<<1, NPAIR>>>(eidx);
    prep_x<<<(TT * ND / 4) / 256, 256>>>(x);
    dummy_kernel<<<1, 32>>>();   // keeps ncu's profiled slot on gemm1

    dim3 g1(NH / 128, NPAIR / 128, NE * 2);   // 22 x 8 x 16
    gemm1_mma<<<g1, 512, G1_SMEM>>>(w1, w3);

    gate_kernel<<<(int)(((size_t)NPAIR * NH / 4) / 256), 256>>>();

    dim3 g2(ND / 64, NPAIR / 128, NE);        // 16 x 8 x 8
    gemm2_mma<<<g2, 512, G2_SMEM>>>(w2, out);
}

// round 11
// speedup vs baseline: 1.6951x; 1.1244x over previous
#include <cuda_runtime.h>
#include <cuda_fp16.h>
#include <stdint.h>

#define TT    512
#define TOPK  2
#define NE    8
#define NH    2816
#define ND    1024
#define NPAIR 1024

// Scratch
__device__ int d_cnt[NE];
__device__ int d_slot[NE][NPAIR];
__device__ __align__(16) float  d_H1[(size_t)NPAIR * NH];
__device__ __align__(16) float  d_H3[(size_t)NPAIR * NH];
__device__ __align__(16) __half d_Gh[(size_t)NPAIR * NH];
__device__ __align__(16) __half d_xh[TT * ND];
__device__ __align__(16) __half d_w1h[(size_t)NE * NH * ND];
__device__ __align__(16) __half d_w3h[(size_t)NE * NH * ND];
__device__ __align__(16) __half d_w2t[(size_t)NE * ND * NH];   // transposed [e][d][h]

// ---------------------------------------------------------------------------
__device__ __forceinline__ uint32_t smem_u32(const void* p) {
    uint32_t a;
    asm("{ .reg .u64 t; cvta.to.shared.u64 t, %1; cvt.u32.u64 %0, t; }" : "=r"(a) : "l"(p));
    return a;
}
__device__ __forceinline__ void ldsm4(uint32_t* r, uint32_t addr) {
    asm volatile("ldmatrix.sync.aligned.m8n8.x4.shared.b16 {%0,%1,%2,%3}, [%4];"
        : "=r"(r[0]), "=r"(r[1]), "=r"(r[2]), "=r"(r[3]) : "r"(addr));
}
__device__ __forceinline__ void mma16816h(float* c, const uint32_t* a, const uint32_t* b) {
    asm volatile("mma.sync.aligned.m16n8k16.row.col.f32.f16.f16.f32 "
        "{%0,%1,%2,%3},{%4,%5,%6,%7},{%8,%9},{%0,%1,%2,%3};"
        : "+f"(c[0]), "+f"(c[1]), "+f"(c[2]), "+f"(c[3])
        : "r"(a[0]), "r"(a[1]), "r"(a[2]), "r"(a[3]), "r"(b[0]), "r"(b[1]));
}
__device__ __forceinline__ void cp16(uint32_t dst, const void* src) {
    asm volatile("cp.async.cg.shared.global [%0], [%1], 16;" :: "r"(dst), "l"(src) : "memory");
}
#define CP_COMMIT() asm volatile("cp.async.commit_group;" ::: "memory")
#define CP_WAIT2()  asm volatile("cp.async.wait_group 2;" ::: "memory")

__device__ __forceinline__ uint32_t pack2h(__half e0, __half e1) {
    return (uint32_t)__half_as_ushort(e0) | ((uint32_t)__half_as_ushort(e1) << 16);
}

// ---------------------------------------------------------------------------
__global__ void route_kernel(const int* __restrict__ eidx) {
    __shared__ int s_cnt[NE];
    int tid = threadIdx.x;
    if (tid < NE) s_cnt[tid] = 0;
    __syncthreads();
    int e = eidx[tid];
    int slot = atomicAdd(&s_cnt[e], 1);
    d_slot[e][slot] = tid;
    __syncthreads();
    if (tid < NE) d_cnt[tid] = s_cnt[tid];
}

__global__ void prep_x(const float* __restrict__ x) {
    size_t i = ((size_t)blockIdx.x * blockDim.x + threadIdx.x) * 4;
    float4 v = *(const float4*)(x + i);
    *(uint2*)(d_xh + i) = make_uint2(pack2h(__float2half_rn(v.x), __float2half_rn(v.y)),
                                     pack2h(__float2half_rn(v.z), __float2half_rn(v.w)));
}

// Combined weight prep: blocks [0, W16_BLOCKS) convert w1/w3 elementwise;
// remaining blocks tile-transpose+convert w2 -> w2t[e][d][h].
#define W16_BLOCKS 45056   // 2 tensors * 23068672 elems / 4 / 256
__global__ __launch_bounds__(256) void prep_w(
    const float* __restrict__ w1, const float* __restrict__ w3,
    const float* __restrict__ w2)
{
    __shared__ float sT[64][65];
    int bid = blockIdx.x;
    int tid = threadIdx.x;
    if (bid < W16_BLOCKS) {
        size_t nf4 = (size_t)NE * NH * ND / 4;
        size_t i = (size_t)bid * 256 + tid;
        const float* src = w1; __half* dst = d_w1h;
        if (i >= nf4) { src = w3; dst = d_w3h; i -= nf4; }
        float4 v = ((const float4*)src)[i];
        *(uint2*)(dst + i * 4) =
            make_uint2(pack2h(__float2half_rn(v.x), __float2half_rn(v.y)),
                       pack2h(__float2half_rn(v.z), __float2half_rn(v.w)));
        return;
    }
    int b  = bid - W16_BLOCKS;
    int xd = b & 15;             // d-tile (16 x 64)
    int yh = (b >> 4) % 44;      // h-tile (44 x 64)
    int e  = b / (16 * 44);
    // read 64 h-rows x 64 d (coalesced), stage transposed
    {
        int row = tid >> 2;            // h within tile
        int seg = (tid & 3) * 16;      // d within tile
        const float* src = w2 + ((size_t)e * NH + yh * 64 + row) * ND + xd * 64 + seg;
        float4 a0 = ((const float4*)src)[0];
        float4 a1 = ((const float4*)src)[1];
        float4 a2 = ((const float4*)src)[2];
        float4 a3 = ((const float4*)src)[3];
        float t[16] = { a0.x,a0.y,a0.z,a0.w, a1.x,a1.y,a1.z,a1.w,
                        a2.x,a2.y,a2.z,a2.w, a3.x,a3.y,a3.z,a3.w };
        #pragma unroll
        for (int i = 0; i < 16; i++) sT[seg + i][row] = t[i];
    }
    __syncthreads();
    // write 64 d-rows x 64 h halves (coalesced 128B rows)
    {
        int drow = tid >> 2;
        int hseg = (tid & 3) * 16;
        uint32_t o[8];
        #pragma unroll
        for (int i = 0; i < 8; i++)
            o[i] = pack2h(__float2half_rn(sT[drow][hseg + 2 * i]),
                          __float2half_rn(sT[drow][hseg + 2 * i + 1]));
        __half* dst = d_w2t + ((size_t)e * ND + xd * 64 + drow) * NH + yh * 64 + hseg;
        ((uint4*)dst)[0] = make_uint4(o[0], o[1], o[2], o[3]);
        ((uint4*)dst)[1] = make_uint4(o[4], o[5], o[6], o[7]);
    }
}

__global__ void gate_kernel() {
    size_t i = ((size_t)blockIdx.x * blockDim.x + threadIdx.x) * 4;
    float4 v1 = *(const float4*)(d_H1 + i);
    float4 v3 = *(const float4*)(d_H3 + i);
    float g0 = __fdividef(v1.x, 1.0f + __expf(-v1.x)) * v3.x;
    float g1 = __fdividef(v1.y, 1.0f + __expf(-v1.y)) * v3.y;
    float g2 = __fdividef(v1.z, 1.0f + __expf(-v1.z)) * v3.z;
    float g3 = __fdividef(v1.w, 1.0f + __expf(-v1.w)) * v3.w;
    *(uint2*)(d_Gh + i) = make_uint2(pack2h(__float2half_rn(g0), __float2half_rn(g1)),
                                     pack2h(__float2half_rn(g2), __float2half_rn(g3)));
}

// ---------------------------------------------------------------------------
// GEMM1: C[128 pairs x 128 h] = x_gathered . w{1|3}^T, K=1024 (16 chunks of 64)
// All-fp16 operands via cp.async, 4-stage pipeline (stage 32KB: A 16K, B 16K).
// ---------------------------------------------------------------------------
#define G1_STAGE 32768
#define G1_NSTG  4
#define G1_SMEM  (1024 + G1_NSTG * G1_STAGE)   // 132096

__global__ __launch_bounds__(512) void gemm1_mma(int dummy)
{
    int z = blockIdx.z, e = z >> 1, f = z & 1;
    int cnt = d_cnt[e];
    int trow0 = blockIdx.y * 128;
    if (trow0 >= cnt) return;
    int col0 = blockIdx.x * 128;
    const __half* wsel = f ? d_w3h : d_w1h;
    float* dH = f ? d_H3 : d_H1;

    extern __shared__ char smem[];
    int* s_p   = (int*)smem;
    int* s_tok = (int*)(smem + 512);
    uint32_t sb = smem_u32(smem);

    int tid = threadIdx.x, lane = tid & 31, wid = tid >> 5;
    if (tid < 128) {
        int r = trow0 + tid;
        int p = (r < cnt) ? d_slot[e][r] : d_slot[e][0];
        s_p[tid] = p; s_tok[tid] = p >> 1;
    }
    __syncthreads();

    int arow = tid >> 2, aq = tid & 3;
    uint32_t aswz = (uint32_t)((arow & 7) << 4);
    const __half* xr = d_xh + (size_t)s_tok[arow] * ND + aq * 16;
    const __half* wr = wsel + ((size_t)e * NH + col0 + arow) * ND + aq * 16;
    uint32_t off0 = (uint32_t)arow * 128 + (((uint32_t)(aq * 32)) ^ aswz);
    uint32_t off1 = (uint32_t)arow * 128 + (((uint32_t)(aq * 32 + 16)) ^ aswz);

    float acc[2][4][4];
    #pragma unroll
    for (int a = 0; a < 2; a++)
        #pragma unroll
        for (int b = 0; b < 4; b++)
            #pragma unroll
            for (int c = 0; c < 4; c++) acc[a][b][c] = 0.0f;

    int wm = wid & 3, wn = wid >> 2;

    #define G1_ISSUE(KC, ST) do { \
        uint32_t base = sb + 1024 + (ST) * G1_STAGE; \
        const char* sa = (const char*)(xr + (KC) * 64); \
        const char* sw = (const char*)(wr + (KC) * 64); \
        cp16(base + off0, sa); \
        cp16(base + off1, sa + 16); \
        cp16(base + 16384 + off0, sw); \
        cp16(base + 16384 + off1, sw + 16); \
    } while (0)

    G1_ISSUE(0, 0); CP_COMMIT();
    G1_ISSUE(1, 1); CP_COMMIT();
    G1_ISSUE(2, 2); CP_COMMIT();

    #pragma unroll 1
    for (int kc = 0; kc < 16; kc++) {
        CP_WAIT2();
        __syncthreads();
        if (kc + 3 < 16) G1_ISSUE(kc + 3, (kc + 3) & 3);
        CP_COMMIT();

        uint32_t uAH = sb + 1024 + (kc & 3) * G1_STAGE;
        uint32_t uBH = uAH + 16384;
        #pragma unroll
        for (int ks = 0; ks < 4; ks++) {
            uint32_t Ah[2][4], Bh[2][4];
            int kb = ks * 32;
            #pragma unroll
            for (int mi = 0; mi < 2; mi++) {
                int row = wm * 32 + mi * 16 + (lane & 15);
                uint32_t bb = (uint32_t)(kb + ((lane >> 4) << 4));
                uint32_t off = (uint32_t)row * 128 + (bb ^ (uint32_t)((row & 7) << 4));
                ldsm4(Ah[mi], uAH + off);
            }
            #pragma unroll
            for (int nb = 0; nb < 2; nb++) {
                int row = wn * 32 + nb * 16 + (lane & 7) + (((lane >> 4) & 1) << 3);
                uint32_t bb = (uint32_t)(kb + (((lane >> 3) & 1) << 4));
                uint32_t off = (uint32_t)row * 128 + (bb ^ (uint32_t)((row & 7) << 4));
                ldsm4(Bh[nb], uBH + off);
            }
            #pragma unroll
            for (int mi = 0; mi < 2; mi++)
                #pragma unroll
                for (int nb = 0; nb < 2; nb++) {
                    mma16816h(acc[mi][2 * nb],     Ah[mi], &Bh[nb][0]);
                    mma16816h(acc[mi][2 * nb + 1], Ah[mi], &Bh[nb][2]);
                }
        }
    }
    #undef G1_ISSUE

    int cntLoc = cnt - trow0; if (cntLoc > 128) cntLoc = 128;
    #pragma unroll
    for (int mi = 0; mi < 2; mi++) {
        int r0 = wm * 32 + mi * 16 + (lane >> 2);
        int r1 = r0 + 8;
        #pragma unroll
        for (int ni = 0; ni < 4; ni++) {
            int col = col0 + wn * 32 + ni * 8 + (lane & 3) * 2;
            if (r0 < cntLoc)
                *(float2*)&dH[(size_t)s_p[r0] * NH + col] =
                    make_float2(acc[mi][ni][0], acc[mi][ni][1]);
            if (r1 < cntLoc)
                *(float2*)&dH[(size_t)s_p[r1] * NH + col] =
                    make_float2(acc[mi][ni][2], acc[mi][ni][3]);
        }
    }
}

// ---------------------------------------------------------------------------
// GEMM2: C[128 pairs x 64 d] = G . w2, K=2816 (44 chunks of 64)
// A = Gh (k-major), B = w2t[e][d][h] (k-major). All cp.async, 4 stages
// (stage 24KB: A 16K, B 8K).
// ---------------------------------------------------------------------------
#define G2_STAGE 24576
#define G2_NSTG  4
#define G2_SMEM  (1024 + G2_NSTG * G2_STAGE)   // 99328

__global__ __launch_bounds__(512) void gemm2_mma(float* __restrict__ out)
{
    int e = blockIdx.z;
    int cnt = d_cnt[e];
    int trow0 = blockIdx.y * 128;
    if (trow0 >= cnt) return;
    int col0 = blockIdx.x * 64;

    extern __shared__ char smem[];
    int* s_p = (int*)smem;
    uint32_t sb = smem_u32(smem);

    int tid = threadIdx.x, lane = tid & 31, wid = tid >> 5;
    if (tid < 128) {
        int r = trow0 + tid;
        s_p[tid] = (r < cnt) ? d_slot[e][r] : d_slot[e][0];
    }
    __syncthreads();

    int arow = tid >> 2, aq = tid & 3;
    uint32_t aswz = (uint32_t)((arow & 7) << 4);
    const __half* gr = d_Gh + (size_t)s_p[arow] * NH + aq * 16;
    uint32_t aoff0 = (uint32_t)arow * 128 + (((uint32_t)(aq * 32)) ^ aswz);
    uint32_t aoff1 = (uint32_t)arow * 128 + (((uint32_t)(aq * 32 + 16)) ^ aswz);

    int brow = tid >> 3, bq = tid & 7;
    const __half* br = d_w2t + ((size_t)e * ND + col0 + brow) * NH + bq * 8;
    uint32_t boff = (uint32_t)brow * 128 +
        (((uint32_t)(bq * 16)) ^ (uint32_t)((brow & 7) << 4));

    float acc[2][2][4];
    #pragma unroll
    for (int a = 0; a < 2; a++)
        #pragma unroll
        for (int b = 0; b < 2; b++)
            #pragma unroll
            for (int c = 0; c < 4; c++) acc[a][b][c] = 0.0f;

    int wm = wid & 3, wn = wid >> 2;

    #define G2_ISSUE(KC, ST) do { \
        uint32_t base = sb + 1024 + (ST) * G2_STAGE; \
        const char* sa = (const char*)(gr + (KC) * 64); \
        const char* sw = (const char*)(br + (KC) * 64); \
        cp16(base + aoff0, sa); \
        cp16(base + aoff1, sa + 16); \
        cp16(base + 16384 + boff, sw); \
    } while (0)

    G2_ISSUE(0, 0); CP_COMMIT();
    G2_ISSUE(1, 1); CP_COMMIT();
    G2_ISSUE(2, 2); CP_COMMIT();

    #pragma unroll 1
    for (int kc = 0; kc < 44; kc++) {
        CP_WAIT2();
        __syncthreads();
        if (kc + 3 < 44) G2_ISSUE(kc + 3, (kc + 3) & 3);
        CP_COMMIT();

        uint32_t uAH = sb + 1024 + (kc & 3) * G2_STAGE;
        uint32_t uBH = uAH + 16384;
        #pragma unroll
        for (int ks = 0; ks < 4; ks++) {
            uint32_t Ah[2][4], Bh[4];
            int kb = ks * 32;
            #pragma unroll
            for (int mi = 0; mi < 2; mi++) {
                int row = wm * 32 + mi * 16 + (lane & 15);
                uint32_t bb = (uint32_t)(kb + ((lane >> 4) << 4));
                uint32_t off = (uint32_t)row * 128 + (bb ^ (uint32_t)((row & 7) << 4));
                ldsm4(Ah[mi], uAH + off);
            }
            {
                int row = wn * 16 + (lane & 7) + (((lane >> 4) & 1) << 3);
                uint32_t bb = (uint32_t)(kb + (((lane >> 3) & 1) << 4));
                uint32_t off = (uint32_t)row * 128 + (bb ^ (uint32_t)((row & 7) << 4));
                ldsm4(Bh, uBH + off);
            }
            #pragma unroll
            for (int mi = 0; mi < 2; mi++) {
                mma16816h(acc[mi][0], Ah[mi], &Bh[0]);
                mma16816h(acc[mi][1], Ah[mi], &Bh[2]);
            }
        }
    }
    #undef G2_ISSUE

    int cntLoc = cnt - trow0; if (cntLoc > 128) cntLoc = 128;
    #pragma unroll
    for (int mi = 0; mi < 2; mi++) {
        int r0 = wm * 32 + mi * 16 + (lane >> 2);
        int r1 = r0 + 8;
        #pragma unroll
        for (int ni = 0; ni < 2; ni++) {
            int col = col0 + wn * 16 + ni * 8 + (lane & 3) * 2;
            if (r0 < cntLoc)
                *(float2*)&out[(size_t)s_p[r0] * ND + col] =
                    make_float2(acc[mi][ni][0], acc[mi][ni][1]);
            if (r1 < cntLoc)
                *(float2*)&out[(size_t)s_p[r1] * ND + col] =
                    make_float2(acc[mi][ni][2], acc[mi][ni][3]);
        }
    }
}

// ---------------------------------------------------------------------------
extern "C" void kernel_launch(void* const* d_in, const int* in_sizes, int n_in,
                              void* d_out, int out_size) {
    const float* x    = (const float*)d_in[0];
    const int*   eidx = (const int*)d_in[1];   // int32 (JAX default int)
    const float* w1   = (const float*)d_in[2];
    const float* w2   = (const float*)d_in[3];
    const float* w3   = (const float*)d_in[4];
    float*       out  = (float*)d_out;

    static bool attr_done = false;
    if (!attr_done) {
        cudaFuncSetAttribute(gemm1_mma, cudaFuncAttributeMaxDynamicSharedMemorySize, G1_SMEM);
        cudaFuncSetAttribute(gemm2_mma, cudaFuncAttributeMaxDynamicSharedMemorySize, G2_SMEM);
        attr_done = true;
    }

    route_kernel<<<1, NPAIR>>>(eidx);
    prep_x<<<(TT * ND / 4) / 256, 256>>>(x);
    prep_w<<<W16_BLOCKS + 16 * 44 * NE, 256>>>(w1, w3, w2);

    dim3 g1(NH / 128, NPAIR / 128, NE * 2);   // 22 x 8 x 16
    gemm1_mma<<<g1, 512, G1_SMEM>>>(0);

    gate_kernel<<<(int)(((size_t)NPAIR * NH / 4) / 256), 256>>>();

    dim3 g2(ND / 64, NPAIR / 128, NE);        // 16 x 8 x 8
    gemm2_mma<<<g2, 512, G2_SMEM>>>(out);
}

// round 12
// speedup vs baseline: 1.7069x; 1.0070x over previous
#include <cuda_runtime.h>
#include <cuda_fp16.h>
#include <stdint.h>

#define TT    512
#define TOPK  2
#define NE    8
#define NH    2816
#define ND    1024
#define NPAIR 1024

// Scratch
__device__ int d_cnt[NE];
__device__ int d_slot[NE][NPAIR];
__device__ __align__(16) float  d_H1[(size_t)NPAIR * NH];
__device__ __align__(16) float  d_H3[(size_t)NPAIR * NH];
__device__ __align__(16) __half d_Gh[(size_t)NPAIR * NH];
__device__ __align__(16) __half d_xh[TT * ND];
__device__ __align__(16) __half d_w1h[(size_t)NE * NH * ND];
__device__ __align__(16) __half d_w3h[(size_t)NE * NH * ND];
__device__ __align__(16) __half d_w2t[(size_t)NE * ND * NH];   // transposed [e][d][h]

// ---------------------------------------------------------------------------
__device__ __forceinline__ uint32_t smem_u32(const void* p) {
    uint32_t a;
    asm("{ .reg .u64 t; cvta.to.shared.u64 t, %1; cvt.u32.u64 %0, t; }" : "=r"(a) : "l"(p));
    return a;
}
__device__ __forceinline__ void ldsm4(uint32_t* r, uint32_t addr) {
    asm volatile("ldmatrix.sync.aligned.m8n8.x4.shared.b16 {%0,%1,%2,%3}, [%4];"
        : "=r"(r[0]), "=r"(r[1]), "=r"(r[2]), "=r"(r[3]) : "r"(addr));
}
__device__ __forceinline__ void mma16816h(float* c, const uint32_t* a, const uint32_t* b) {
    asm volatile("mma.sync.aligned.m16n8k16.row.col.f32.f16.f16.f32 "
        "{%0,%1,%2,%3},{%4,%5,%6,%7},{%8,%9},{%0,%1,%2,%3};"
        : "+f"(c[0]), "+f"(c[1]), "+f"(c[2]), "+f"(c[3])
        : "r"(a[0]), "r"(a[1]), "r"(a[2]), "r"(a[3]), "r"(b[0]), "r"(b[1]));
}
__device__ __forceinline__ void cp16(uint32_t dst, const void* src) {
    asm volatile("cp.async.cg.shared.global [%0], [%1], 16;" :: "r"(dst), "l"(src) : "memory");
}
#define CP_COMMIT() asm volatile("cp.async.commit_group;" ::: "memory")
#define CP_WAIT2()  asm volatile("cp.async.wait_group 2;" ::: "memory")

__device__ __forceinline__ uint32_t pack2h(__half e0, __half e1) {
    return (uint32_t)__half_as_ushort(e0) | ((uint32_t)__half_as_ushort(e1) << 16);
}

// ---------------------------------------------------------------------------
__global__ void route_kernel(const int* __restrict__ eidx) {
    __shared__ int s_cnt[NE];
    int tid = threadIdx.x;
    if (tid < NE) s_cnt[tid] = 0;
    __syncthreads();
    int e = eidx[tid];
    int slot = atomicAdd(&s_cnt[e], 1);
    d_slot[e][slot] = tid;
    __syncthreads();
    if (tid < NE) d_cnt[tid] = s_cnt[tid];
}

__global__ void prep_x(const float* __restrict__ x) {
    size_t i = ((size_t)blockIdx.x * blockDim.x + threadIdx.x) * 4;
    float4 v = *(const float4*)(x + i);
    *(uint2*)(d_xh + i) = make_uint2(pack2h(__float2half_rn(v.x), __float2half_rn(v.y)),
                                     pack2h(__float2half_rn(v.z), __float2half_rn(v.w)));
}

// Combined weight prep: blocks [0, W16_BLOCKS) convert w1/w3 elementwise;
// remaining blocks tile-transpose+convert w2 -> w2t[e][d][h].
#define W16_BLOCKS 45056   // 2 tensors * 23068672 elems / 4 / 256
__global__ __launch_bounds__(256) void prep_w(
    const float* __restrict__ w1, const float* __restrict__ w3,
    const float* __restrict__ w2)
{
    __shared__ float sT[64][65];
    int bid = blockIdx.x;
    int tid = threadIdx.x;
    if (bid < W16_BLOCKS) {
        size_t nf4 = (size_t)NE * NH * ND / 4;
        size_t i = (size_t)bid * 256 + tid;
        const float* src = w1; __half* dst = d_w1h;
        if (i >= nf4) { src = w3; dst = d_w3h; i -= nf4; }
        float4 v = ((const float4*)src)[i];
        *(uint2*)(dst + i * 4) =
            make_uint2(pack2h(__float2half_rn(v.x), __float2half_rn(v.y)),
                       pack2h(__float2half_rn(v.z), __float2half_rn(v.w)));
        return;
    }
    int b  = bid - W16_BLOCKS;
    int xd = b & 15;             // d-tile (16 x 64)
    int yh = (b >> 4) % 44;      // h-tile (44 x 64)
    int e  = b / (16 * 44);
    // read 64 h-rows x 64 d (coalesced), stage transposed
    {
        int row = tid >> 2;            // h within tile
        int seg = (tid & 3) * 16;      // d within tile
        const float* src = w2 + ((size_t)e * NH + yh * 64 + row) * ND + xd * 64 + seg;
        float4 a0 = ((const float4*)src)[0];
        float4 a1 = ((const float4*)src)[1];
        float4 a2 = ((const float4*)src)[2];
        float4 a3 = ((const float4*)src)[3];
        float t[16] = { a0.x,a0.y,a0.z,a0.w, a1.x,a1.y,a1.z,a1.w,
                        a2.x,a2.y,a2.z,a2.w, a3.x,a3.y,a3.z,a3.w };
        #pragma unroll
        for (int i = 0; i < 16; i++) sT[seg + i][row] = t[i];
    }
    __syncthreads();
    // write 64 d-rows x 64 h halves (coalesced 128B rows)
    {
        int drow = tid >> 2;
        int hseg = (tid & 3) * 16;
        uint32_t o[8];
        #pragma unroll
        for (int i = 0; i < 8; i++)
            o[i] = pack2h(__float2half_rn(sT[drow][hseg + 2 * i]),
                          __float2half_rn(sT[drow][hseg + 2 * i + 1]));
        __half* dst = d_w2t + ((size_t)e * ND + xd * 64 + drow) * NH + yh * 64 + hseg;
        ((uint4*)dst)[0] = make_uint4(o[0], o[1], o[2], o[3]);
        ((uint4*)dst)[1] = make_uint4(o[4], o[5], o[6], o[7]);
    }
}

__global__ void gate_kernel() {
    size_t i = ((size_t)blockIdx.x * blockDim.x + threadIdx.x) * 4;
    float4 v1 = *(const float4*)(d_H1 + i);
    float4 v3 = *(const float4*)(d_H3 + i);
    float g0 = __fdividef(v1.x, 1.0f + __expf(-v1.x)) * v3.x;
    float g1 = __fdividef(v1.y, 1.0f + __expf(-v1.y)) * v3.y;
    float g2 = __fdividef(v1.z, 1.0f + __expf(-v1.z)) * v3.z;
    float g3 = __fdividef(v1.w, 1.0f + __expf(-v1.w)) * v3.w;
    *(uint2*)(d_Gh + i) = make_uint2(pack2h(__float2half_rn(g0), __float2half_rn(g1)),
                                     pack2h(__float2half_rn(g2), __float2half_rn(g3)));
}

// ---------------------------------------------------------------------------
// GEMM1: C[128 pairs x 128 h] = x_gathered . w{1|3}^T, K=1024 (16 chunks of 64)
// All-fp16 operands via cp.async, 4-stage pipeline (stage 32KB: A 16K, B 16K).
// ---------------------------------------------------------------------------
#define G1_STAGE 32768
#define G1_NSTG  4
#define G1_SMEM  (1024 + G1_NSTG * G1_STAGE)   // 132096

__global__ __launch_bounds__(512) void gemm1_mma(int dummy)
{
    int z = blockIdx.z, e = z >> 1, f = z & 1;
    int cnt = d_cnt[e];
    int trow0 = blockIdx.y * 128;
    if (trow0 >= cnt) return;
    int col0 = blockIdx.x * 128;
    const __half* wsel = f ? d_w3h : d_w1h;
    float* dH = f ? d_H3 : d_H1;

    extern __shared__ char smem[];
    int* s_p   = (int*)smem;
    int* s_tok = (int*)(smem + 512);
    uint32_t sb = smem_u32(smem);

    int tid = threadIdx.x, lane = tid & 31, wid = tid >> 5;
    if (tid < 128) {
        int r = trow0 + tid;
        int p = (r < cnt) ? d_slot[e][r] : d_slot[e][0];
        s_p[tid] = p; s_tok[tid] = p >> 1;
    }
    __syncthreads();

    int arow = tid >> 2, aq = tid & 3;
    uint32_t aswz = (uint32_t)((arow & 7) << 4);
    const __half* xr = d_xh + (size_t)s_tok[arow] * ND + aq * 16;
    const __half* wr = wsel + ((size_t)e * NH + col0 + arow) * ND + aq * 16;
    uint32_t off0 = (uint32_t)arow * 128 + (((uint32_t)(aq * 32)) ^ aswz);
    uint32_t off1 = (uint32_t)arow * 128 + (((uint32_t)(aq * 32 + 16)) ^ aswz);

    float acc[2][4][4];
    #pragma unroll
    for (int a = 0; a < 2; a++)
        #pragma unroll
        for (int b = 0; b < 4; b++)
            #pragma unroll
            for (int c = 0; c < 4; c++) acc[a][b][c] = 0.0f;

    int wm = wid & 3, wn = wid >> 2;

    #define G1_ISSUE(KC, ST) do { \
        uint32_t base = sb + 1024 + (ST) * G1_STAGE; \
        const char* sa = (const char*)(xr + (KC) * 64); \
        const char* sw = (const char*)(wr + (KC) * 64); \
        cp16(base + off0, sa); \
        cp16(base + off1, sa + 16); \
        cp16(base + 16384 + off0, sw); \
        cp16(base + 16384 + off1, sw + 16); \
    } while (0)

    G1_ISSUE(0, 0); CP_COMMIT();
    G1_ISSUE(1, 1); CP_COMMIT();
    G1_ISSUE(2, 2); CP_COMMIT();

    #pragma unroll 1
    for (int kc = 0; kc < 16; kc++) {
        CP_WAIT2();
        __syncthreads();
        if (kc + 3 < 16) G1_ISSUE(kc + 3, (kc + 3) & 3);
        CP_COMMIT();

        uint32_t uAH = sb + 1024 + (kc & 3) * G1_STAGE;
        uint32_t uBH = uAH + 16384;
        #pragma unroll
        for (int ks = 0; ks < 4; ks++) {
            uint32_t Ah[2][4], Bh[2][4];
            int kb = ks * 32;
            #pragma unroll
            for (int mi = 0; mi < 2; mi++) {
                int row = wm * 32 + mi * 16 + (lane & 15);
                uint32_t bb = (uint32_t)(kb + ((lane >> 4) << 4));
                uint32_t off = (uint32_t)row * 128 + (bb ^ (uint32_t)((row & 7) << 4));
                ldsm4(Ah[mi], uAH + off);
            }
            #pragma unroll
            for (int nb = 0; nb < 2; nb++) {
                int row = wn * 32 + nb * 16 + (lane & 7) + (((lane >> 4) & 1) << 3);
                uint32_t bb = (uint32_t)(kb + (((lane >> 3) & 1) << 4));
                uint32_t off = (uint32_t)row * 128 + (bb ^ (uint32_t)((row & 7) << 4));
                ldsm4(Bh[nb], uBH + off);
            }
            #pragma unroll
            for (int mi = 0; mi < 2; mi++)
                #pragma unroll
                for (int nb = 0; nb < 2; nb++) {
                    mma16816h(acc[mi][2 * nb],     Ah[mi], &Bh[nb][0]);
                    mma16816h(acc[mi][2 * nb + 1], Ah[mi], &Bh[nb][2]);
                }
        }
    }
    #undef G1_ISSUE

    int cntLoc = cnt - trow0; if (cntLoc > 128) cntLoc = 128;
    #pragma unroll
    for (int mi = 0; mi < 2; mi++) {
        int r0 = wm * 32 + mi * 16 + (lane >> 2);
        int r1 = r0 + 8;
        #pragma unroll
        for (int ni = 0; ni < 4; ni++) {
            int col = col0 + wn * 32 + ni * 8 + (lane & 3) * 2;
            if (r0 < cntLoc)
                *(float2*)&dH[(size_t)s_p[r0] * NH + col] =
                    make_float2(acc[mi][ni][0], acc[mi][ni][1]);
            if (r1 < cntLoc)
                *(float2*)&dH[(size_t)s_p[r1] * NH + col] =
                    make_float2(acc[mi][ni][2], acc[mi][ni][3]);
        }
    }
}

// ---------------------------------------------------------------------------
// GEMM2: C[128 pairs x 64 d] = G . w2, K=2816 (44 chunks of 64)
// A = Gh (k-major), B = w2t[e][d][h] (k-major). All cp.async, 4 stages
// (stage 24KB: A 16K, B 8K).
// ---------------------------------------------------------------------------
#define G2_STAGE 24576
#define G2_NSTG  4
#define G2_SMEM  (1024 + G2_NSTG * G2_STAGE)   // 99328

__global__ __launch_bounds__(512) void gemm2_mma(float* __restrict__ out)
{
    int e = blockIdx.z;
    int cnt = d_cnt[e];
    int trow0 = blockIdx.y * 128;
    if (trow0 >= cnt) return;
    int col0 = blockIdx.x * 64;

    extern __shared__ char smem[];
    int* s_p = (int*)smem;
    uint32_t sb = smem_u32(smem);

    int tid = threadIdx.x, lane = tid & 31, wid = tid >> 5;
    if (tid < 128) {
        int r = trow0 + tid;
        s_p[tid] = (r < cnt) ? d_slot[e][r] : d_slot[e][0];
    }
    __syncthreads();

    int arow = tid >> 2, aq = tid & 3;
    uint32_t aswz = (uint32_t)((arow & 7) << 4);
    const __half* gr = d_Gh + (size_t)s_p[arow] * NH + aq * 16;
    uint32_t aoff0 = (uint32_t)arow * 128 + (((uint32_t)(aq * 32)) ^ aswz);
    uint32_t aoff1 = (uint32_t)arow * 128 + (((uint32_t)(aq * 32 + 16)) ^ aswz);

    int brow = tid >> 3, bq = tid & 7;
    const __half* br = d_w2t + ((size_t)e * ND + col0 + brow) * NH + bq * 8;
    uint32_t boff = (uint32_t)brow * 128 +
        (((uint32_t)(bq * 16)) ^ (uint32_t)((brow & 7) << 4));

    float acc[2][2][4];
    #pragma unroll
    for (int a = 0; a < 2; a++)
        #pragma unroll
        for (int b = 0; b < 2; b++)
            #pragma unroll
            for (int c = 0; c < 4; c++) acc[a][b][c] = 0.0f;

    int wm = wid & 3, wn = wid >> 2;

    #define G2_ISSUE(KC, ST) do { \
        uint32_t base = sb + 1024 + (ST) * G2_STAGE; \
        const char* sa = (const char*)(gr + (KC) * 64); \
        const char* sw = (const char*)(br + (KC) * 64); \
        cp16(base + aoff0, sa); \
        cp16(base + aoff1, sa + 16); \
        cp16(base + 16384 + boff, sw); \
    } while (0)

    G2_ISSUE(0, 0); CP_COMMIT();
    G2_ISSUE(1, 1); CP_COMMIT();
    G2_ISSUE(2, 2); CP_COMMIT();

    #pragma unroll 1
    for (int kc = 0; kc < 44; kc++) {
        CP_WAIT2();
        __syncthreads();
        if (kc + 3 < 44) G2_ISSUE(kc + 3, (kc + 3) & 3);
        CP_COMMIT();

        uint32_t uAH = sb + 1024 + (kc & 3) * G2_STAGE;
        uint32_t uBH = uAH + 16384;
        #pragma unroll
        for (int ks = 0; ks < 4; ks++) {
            uint32_t Ah[2][4], Bh[4];
            int kb = ks * 32;
            #pragma unroll
            for (int mi = 0; mi < 2; mi++) {
                int row = wm * 32 + mi * 16 + (lane & 15);
                uint32_t bb = (uint32_t)(kb + ((lane >> 4) << 4));
                uint32_t off = (uint32_t)row * 128 + (bb ^ (uint32_t)((row & 7) << 4));
                ldsm4(Ah[mi], uAH + off);
            }
            {
                int row = wn * 16 + (lane & 7) + (((lane >> 4) & 1) << 3);
                uint32_t bb = (uint32_t)(kb + (((lane >> 3) & 1) << 4));
                uint32_t off = (uint32_t)row * 128 + (bb ^ (uint32_t)((row & 7) << 4));
                ldsm4(Bh, uBH + off);
            }
            #pragma unroll
            for (int mi = 0; mi < 2; mi++) {
                mma16816h(acc[mi][0], Ah[mi], &Bh[0]);
                mma16816h(acc[mi][1], Ah[mi], &Bh[2]);
            }
        }
    }
    #undef G2_ISSUE

    int cntLoc = cnt - trow0; if (cntLoc > 128) cntLoc = 128;
    #pragma unroll
    for (int mi = 0; mi < 2; mi++) {
        int r0 = wm * 32 + mi * 16 + (lane >> 2);
        int r1 = r0 + 8;
        #pragma unroll
        for (int ni = 0; ni < 2; ni++) {
            int col = col0 + wn * 16 + ni * 8 + (lane & 3) * 2;
            if (r0 < cntLoc)
                *(float2*)&out[(size_t)s_p[r0] * ND + col] =
                    make_float2(acc[mi][ni][0], acc[mi][ni][1]);
            if (r1 < cntLoc)
                *(float2*)&out[(size_t)s_p[r1] * ND + col] =
                    make_float2(acc[mi][ni][2], acc[mi][ni][3]);
        }
    }
}

// ---------------------------------------------------------------------------
extern "C" void kernel_launch(void* const* d_in, const int* in_sizes, int n_in,
                              void* d_out, int out_size) {
    const float* x    = (const float*)d_in[0];
    const int*   eidx = (const int*)d_in[1];   // int32 (JAX default int)
    const float* w1   = (const float*)d_in[2];
    const float* w2   = (const float*)d_in[3];
    const float* w3   = (const float*)d_in[4];
    float*       out  = (float*)d_out;

    static bool attr_done = false;
    if (!attr_done) {
        cudaFuncSetAttribute(gemm1_mma, cudaFuncAttributeMaxDynamicSharedMemorySize, G1_SMEM);
        cudaFuncSetAttribute(gemm2_mma, cudaFuncAttributeMaxDynamicSharedMemorySize, G2_SMEM);
        attr_done = true;
    }

    route_kernel<<<1, NPAIR>>>(eidx);
    prep_x<<<(TT * ND / 4) / 256, 256>>>(x);
    prep_w<<<W16_BLOCKS + 16 * 44 * NE, 256>>>(w1, w3, w2);

    dim3 g1(NH / 128, NPAIR / 128, NE * 2);   // 22 x 8 x 16
    gemm1_mma<<<g1, 512, G1_SMEM>>>(0);

    gate_kernel<<<(int)(((size_t)NPAIR * NH / 4) / 256), 256>>>();

    dim3 g2(ND / 64, NPAIR / 128, NE);        // 16 x 8 x 8
    gemm2_mma<<<g2, 512, G2_SMEM>>>(out);
}

// round 13
// speedup vs baseline: 1.7229x; 1.0094x over previous
#include <cuda_runtime.h>
#include <cuda_fp16.h>
#include <stdint.h>

#define TT    512
#define TOPK  2
#define NE    8
#define NH    2816
#define ND    1024
#define NPAIR 1024

// Scratch
__device__ int d_cnt[NE];
__device__ int d_slot[NE][NPAIR];
__device__ __align__(16) float  d_H1[(size_t)NPAIR * NH];
__device__ __align__(16) float  d_H3[(size_t)NPAIR * NH];
__device__ __align__(16) __half d_Gh[(size_t)NPAIR * NH];
__device__ __align__(16) __half d_xh[TT * ND];
__device__ __align__(16) __half d_w1h[(size_t)NE * NH * ND];
__device__ __align__(16) __half d_w3h[(size_t)NE * NH * ND];
__device__ __align__(16) __half d_w2t[(size_t)NE * ND * NH];   // transposed [e][d][h]

// ---------------------------------------------------------------------------
__device__ __forceinline__ uint32_t smem_u32(const void* p) {
    uint32_t a;
    asm("{ .reg .u64 t; cvta.to.shared.u64 t, %1; cvt.u32.u64 %0, t; }" : "=r"(a) : "l"(p));
    return a;
}
__device__ __forceinline__ void ldsm4(uint32_t* r, uint32_t addr) {
    asm volatile("ldmatrix.sync.aligned.m8n8.x4.shared.b16 {%0,%1,%2,%3}, [%4];"
        : "=r"(r[0]), "=r"(r[1]), "=r"(r[2]), "=r"(r[3]) : "r"(addr));
}
__device__ __forceinline__ void mma16816h(float* c, const uint32_t* a, const uint32_t* b) {
    asm volatile("mma.sync.aligned.m16n8k16.row.col.f32.f16.f16.f32 "
        "{%0,%1,%2,%3},{%4,%5,%6,%7},{%8,%9},{%0,%1,%2,%3};"
        : "+f"(c[0]), "+f"(c[1]), "+f"(c[2]), "+f"(c[3])
        : "r"(a[0]), "r"(a[1]), "r"(a[2]), "r"(a[3]), "r"(b[0]), "r"(b[1]));
}
__device__ __forceinline__ void cp16(uint32_t dst, const void* src) {
    asm volatile("cp.async.cg.shared.global [%0], [%1], 16;" :: "r"(dst), "l"(src) : "memory");
}
#define CP_COMMIT() asm volatile("cp.async.commit_group;" ::: "memory")
#define CP_WAIT2()  asm volatile("cp.async.wait_group 2;" ::: "memory")

__device__ __forceinline__ uint32_t pack2h(__half e0, __half e1) {
    return (uint32_t)__half_as_ushort(e0) | ((uint32_t)__half_as_ushort(e1) << 16);
}

// ---------------------------------------------------------------------------
__global__ void route_kernel(const int* __restrict__ eidx) {
    __shared__ int s_cnt[NE];
    int tid = threadIdx.x;
    if (tid < NE) s_cnt[tid] = 0;
    __syncthreads();
    int e = eidx[tid];
    int slot = atomicAdd(&s_cnt[e], 1);
    d_slot[e][slot] = tid;
    __syncthreads();
    if (tid < NE) d_cnt[tid] = s_cnt[tid];
}

__global__ void prep_x(const float* __restrict__ x) {
    size_t i = ((size_t)blockIdx.x * blockDim.x + threadIdx.x) * 4;
    float4 v = *(const float4*)(x + i);
    *(uint2*)(d_xh + i) = make_uint2(pack2h(__float2half_rn(v.x), __float2half_rn(v.y)),
                                     pack2h(__float2half_rn(v.z), __float2half_rn(v.w)));
}

#define W16_BLOCKS 45056
__global__ __launch_bounds__(256) void prep_w(
    const float* __restrict__ w1, const float* __restrict__ w3,
    const float* __restrict__ w2)
{
    __shared__ float sT[64][65];
    int bid = blockIdx.x;
    int tid = threadIdx.x;
    if (bid < W16_BLOCKS) {
        size_t nf4 = (size_t)NE * NH * ND / 4;
        size_t i = (size_t)bid * 256 + tid;
        const float* src = w1; __half* dst = d_w1h;
        if (i >= nf4) { src = w3; dst = d_w3h; i -= nf4; }
        float4 v = ((const float4*)src)[i];
        *(uint2*)(dst + i * 4) =
            make_uint2(pack2h(__float2half_rn(v.x), __float2half_rn(v.y)),
                       pack2h(__float2half_rn(v.z), __float2half_rn(v.w)));
        return;
    }
    int b  = bid - W16_BLOCKS;
    int xd = b & 15;
    int yh = (b >> 4) % 44;
    int e  = b / (16 * 44);
    {
        int row = tid >> 2;
        int seg = (tid & 3) * 16;
        const float* src = w2 + ((size_t)e * NH + yh * 64 + row) * ND + xd * 64 + seg;
        float4 a0 = ((const float4*)src)[0];
        float4 a1 = ((const float4*)src)[1];
        float4 a2 = ((const float4*)src)[2];
        float4 a3 = ((const float4*)src)[3];
        float t[16] = { a0.x,a0.y,a0.z,a0.w, a1.x,a1.y,a1.z,a1.w,
                        a2.x,a2.y,a2.z,a2.w, a3.x,a3.y,a3.z,a3.w };
        #pragma unroll
        for (int i = 0; i < 16; i++) sT[seg + i][row] = t[i];
    }
    __syncthreads();
    {
        int drow = tid >> 2;
        int hseg = (tid & 3) * 16;
        uint32_t o[8];
        #pragma unroll
        for (int i = 0; i < 8; i++)
            o[i] = pack2h(__float2half_rn(sT[drow][hseg + 2 * i]),
                          __float2half_rn(sT[drow][hseg + 2 * i + 1]));
        __half* dst = d_w2t + ((size_t)e * ND + xd * 64 + drow) * NH + yh * 64 + hseg;
        ((uint4*)dst)[0] = make_uint4(o[0], o[1], o[2], o[3]);
        ((uint4*)dst)[1] = make_uint4(o[4], o[5], o[6], o[7]);
    }
}

__global__ void gate_kernel() {
    size_t i = ((size_t)blockIdx.x * blockDim.x + threadIdx.x) * 4;
    float4 v1 = *(const float4*)(d_H1 + i);
    float4 v3 = *(const float4*)(d_H3 + i);
    float g0 = __fdividef(v1.x, 1.0f + __expf(-v1.x)) * v3.x;
    float g1 = __fdividef(v1.y, 1.0f + __expf(-v1.y)) * v3.y;
    float g2 = __fdividef(v1.z, 1.0f + __expf(-v1.z)) * v3.z;
    float g3 = __fdividef(v1.w, 1.0f + __expf(-v1.w)) * v3.w;
    *(uint2*)(d_Gh + i) = make_uint2(pack2h(__float2half_rn(g0), __float2half_rn(g1)),
                                     pack2h(__float2half_rn(g2), __float2half_rn(g3)));
}

// ---------------------------------------------------------------------------
// GEMM1: C[128 pairs x 128 h] = x_gathered . w{1|3}^T, K=1024 (16 chunks of 64)
// 3-stage pipeline (stage 32KB: A 16K, B 16K), 2 CTAs/SM.
// ---------------------------------------------------------------------------
#define G1_STAGE 32768
#define G1_SMEM  (1024 + 3 * G1_STAGE)   // 99328

__global__ __launch_bounds__(512, 2) void gemm1_mma(int dummy)
{
    int z = blockIdx.z, e = z >> 1, f = z & 1;
    int cnt = d_cnt[e];
    int trow0 = blockIdx.y * 128;
    if (trow0 >= cnt) return;
    int col0 = blockIdx.x * 128;
    const __half* wsel = f ? d_w3h : d_w1h;
    float* dH = f ? d_H3 : d_H1;

    extern __shared__ char smem[];
    int* s_p   = (int*)smem;
    int* s_tok = (int*)(smem + 512);
    uint32_t sb = smem_u32(smem);

    int tid = threadIdx.x, lane = tid & 31, wid = tid >> 5;
    if (tid < 128) {
        int r = trow0 + tid;
        int p = (r < cnt) ? d_slot[e][r] : d_slot[e][0];
        s_p[tid] = p; s_tok[tid] = p >> 1;
    }
    __syncthreads();

    int arow = tid >> 2, aq = tid & 3;
    uint32_t aswz = (uint32_t)((arow & 7) << 4);
    const __half* xr = d_xh + (size_t)s_tok[arow] * ND + aq * 16;
    const __half* wr = wsel + ((size_t)e * NH + col0 + arow) * ND + aq * 16;
    uint32_t off0 = (uint32_t)arow * 128 + (((uint32_t)(aq * 32)) ^ aswz);
    uint32_t off1 = (uint32_t)arow * 128 + (((uint32_t)(aq * 32 + 16)) ^ aswz);

    float acc[2][4][4];
    #pragma unroll
    for (int a = 0; a < 2; a++)
        #pragma unroll
        for (int b = 0; b < 4; b++)
            #pragma unroll
            for (int c = 0; c < 4; c++) acc[a][b][c] = 0.0f;

    int wm = wid & 3, wn = wid >> 2;

    #define G1_ISSUE(KC, ST) do { \
        uint32_t base = sb + 1024 + (ST) * G1_STAGE; \
        const char* sa = (const char*)(xr + (KC) * 64); \
        const char* sw = (const char*)(wr + (KC) * 64); \
        cp16(base + off0, sa); \
        cp16(base + off1, sa + 16); \
        cp16(base + 16384 + off0, sw); \
        cp16(base + 16384 + off1, sw + 16); \
    } while (0)

    G1_ISSUE(0, 0); CP_COMMIT();
    G1_ISSUE(1, 1); CP_COMMIT();
    G1_ISSUE(2, 2); CP_COMMIT();

    int st = 0;
    #pragma unroll 1
    for (int kc = 0; kc < 16; kc++) {
        CP_WAIT2();
        __syncthreads();

        uint32_t uAH = sb + 1024 + st * G1_STAGE;
        uint32_t uBH = uAH + 16384;
        #pragma unroll
        for (int ks = 0; ks < 4; ks++) {
            uint32_t Ah[2][4], Bh[2][4];
            int kb = ks * 32;
            #pragma unroll
            for (int mi = 0; mi < 2; mi++) {
                int row = wm * 32 + mi * 16 + (lane & 15);
                uint32_t bb = (uint32_t)(kb + ((lane >> 4) << 4));
                uint32_t off = (uint32_t)row * 128 + (bb ^ (uint32_t)((row & 7) << 4));
                ldsm4(Ah[mi], uAH + off);
            }
            #pragma unroll
            for (int nb = 0; nb < 2; nb++) {
                int row = wn * 32 + nb * 16 + (lane & 7) + (((lane >> 4) & 1) << 3);
                uint32_t bb = (uint32_t)(kb + (((lane >> 3) & 1) << 4));
                uint32_t off = (uint32_t)row * 128 + (bb ^ (uint32_t)((row & 7) << 4));
                ldsm4(Bh[nb], uBH + off);
            }
            #pragma unroll
            for (int mi = 0; mi < 2; mi++)
                #pragma unroll
                for (int nb = 0; nb < 2; nb++) {
                    mma16816h(acc[mi][2 * nb],     Ah[mi], &Bh[nb][0]);
                    mma16816h(acc[mi][2 * nb + 1], Ah[mi], &Bh[nb][2]);
                }
        }
        __syncthreads();
        if (kc + 3 < 16) G1_ISSUE(kc + 3, st);
        CP_COMMIT();
        st = (st == 2) ? 0 : st + 1;
    }
    #undef G1_ISSUE

    int cntLoc = cnt - trow0; if (cntLoc > 128) cntLoc = 128;
    #pragma unroll
    for (int mi = 0; mi < 2; mi++) {
        int r0 = wm * 32 + mi * 16 + (lane >> 2);
        int r1 = r0 + 8;
        #pragma unroll
        for (int ni = 0; ni < 4; ni++) {
            int col = col0 + wn * 32 + ni * 8 + (lane & 3) * 2;
            if (r0 < cntLoc)
                *(float2*)&dH[(size_t)s_p[r0] * NH + col] =
                    make_float2(acc[mi][ni][0], acc[mi][ni][1]);
            if (r1 < cntLoc)
                *(float2*)&dH[(size_t)s_p[r1] * NH + col] =
                    make_float2(acc[mi][ni][2], acc[mi][ni][3]);
        }
    }
}

// ---------------------------------------------------------------------------
// GEMM2: C[64 pairs x 64 d] = G . w2t, K=2816 (44 chunks of 64)
// 512 threads, warp grid 4x4 (each 16x16). 3-stage pipeline
// (stage 16KB: A 8K, B 8K), 2 CTAs/SM.
// ---------------------------------------------------------------------------
#define G2_STAGE 16384
#define G2_SMEM  (1024 + 3 * G2_STAGE)   // 50176

__global__ __launch_bounds__(512, 2) void gemm2_mma(float* __restrict__ out)
{
    int e = blockIdx.z;
    int cnt = d_cnt[e];
    int trow0 = blockIdx.y * 64;
    if (trow0 >= cnt) return;
    int col0 = blockIdx.x * 64;

    extern __shared__ char smem[];
    int* s_p = (int*)smem;
    uint32_t sb = smem_u32(smem);

    int tid = threadIdx.x, lane = tid & 31, wid = tid >> 5;
    if (tid < 64) {
        int r = trow0 + tid;
        s_p[tid] = (r < cnt) ? d_slot[e][r] : d_slot[e][0];
    }
    __syncthreads();

    // loaders: 64 rows x 128B per operand; thread t loads 16B
    int lrow = tid >> 3, lq = tid & 7;
    uint32_t loff = (uint32_t)lrow * 128 +
        (((uint32_t)(lq * 16)) ^ (uint32_t)((lrow & 7) << 4));
    const __half* gr = d_Gh + (size_t)s_p[lrow] * NH + lq * 8;
    const __half* br = d_w2t + ((size_t)e * ND + col0 + lrow) * NH + lq * 8;

    float acc[2][4];
    #pragma unroll
    for (int b = 0; b < 2; b++)
        #pragma unroll
        for (int c = 0; c < 4; c++) acc[b][c] = 0.0f;

    int wm = wid & 3, wn = wid >> 2;   // 4 x 16 rows, 4 x 16 cols

    #define G2_ISSUE(KC, ST) do { \
        uint32_t base = sb + 1024 + (ST) * G2_STAGE; \
        cp16(base + loff, (const char*)(gr + (KC) * 64)); \
        cp16(base + 8192 + loff, (const char*)(br + (KC) * 64)); \
    } while (0)

    G2_ISSUE(0, 0); CP_COMMIT();
    G2_ISSUE(1, 1); CP_COMMIT();
    G2_ISSUE(2, 2); CP_COMMIT();

    int st = 0;
    #pragma unroll 1
    for (int kc = 0; kc < 44; kc++) {
        CP_WAIT2();
        __syncthreads();

        uint32_t uAH = sb + 1024 + st * G2_STAGE;
        uint32_t uBH = uAH + 8192;
        #pragma unroll
        for (int ks = 0; ks < 4; ks++) {
            uint32_t Ah[4], Bh[4];
            int kb = ks * 32;
            {
                int row = wm * 16 + (lane & 15);
                uint32_t bb = (uint32_t)(kb + ((lane >> 4) << 4));
                uint32_t off = (uint32_t)row * 128 + (bb ^ (uint32_t)((row & 7) << 4));
                ldsm4(Ah, uAH + off);
            }
            {
                int row = wn * 16 + (lane & 7) + (((lane >> 4) & 1) << 3);
                uint32_t bb = (uint32_t)(kb + (((lane >> 3) & 1) << 4));
                uint32_t off = (uint32_t)row * 128 + (bb ^ (uint32_t)((row & 7) << 4));
                ldsm4(Bh, uBH + off);
            }
            mma16816h(acc[0], Ah, &Bh[0]);
            mma16816h(acc[1], Ah, &Bh[2]);
        }
        __syncthreads();
        if (kc + 3 < 44) G2_ISSUE(kc + 3, st);
        CP_COMMIT();
        st = (st == 2) ? 0 : st + 1;
    }
    #undef G2_ISSUE

    int cntLoc = cnt - trow0; if (cntLoc > 64) cntLoc = 64;
    {
        int r0 = wm * 16 + (lane >> 2);
        int r1 = r0 + 8;
        #pragma unroll
        for (int ni = 0; ni < 2; ni++) {
            int col = col0 + wn * 16 + ni * 8 + (lane & 3) * 2;
            if (r0 < cntLoc)
                *(float2*)&out[(size_t)s_p[r0] * ND + col] =
                    make_float2(acc[ni][0], acc[ni][1]);
            if (r1 < cntLoc)
                *(float2*)&out[(size_t)s_p[r1] * ND + col] =
                    make_float2(acc[ni][2], acc[ni][3]);
        }
    }
}

// ---------------------------------------------------------------------------
extern "C" void kernel_launch(void* const* d_in, const int* in_sizes, int n_in,
                              void* d_out, int out_size) {
    const float* x    = (const float*)d_in[0];
    const int*   eidx = (const int*)d_in[1];   // int32 (JAX default int)
    const float* w1   = (const float*)d_in[2];
    const float* w2   = (const float*)d_in[3];
    const float* w3   = (const float*)d_in[4];
    float*       out  = (float*)d_out;

    static bool attr_done = false;
    if (!attr_done) {
        cudaFuncSetAttribute(gemm1_mma, cudaFuncAttributeMaxDynamicSharedMemorySize, G1_SMEM);
        cudaFuncSetAttribute(gemm2_mma, cudaFuncAttributeMaxDynamicSharedMemorySize, G2_SMEM);
        attr_done = true;
    }

    route_kernel<<<1, NPAIR>>>(eidx);
    prep_x<<<(TT * ND / 4) / 256, 256>>>(x);
    prep_w<<<W16_BLOCKS + 16 * 44 * NE, 256>>>(w1, w3, w2);

    dim3 g1(NH / 128, NPAIR / 128, NE * 2);   // 22 x 8 x 16
    gemm1_mma<<<g1, 512, G1_SMEM>>>(0);

    gate_kernel<<<(int)(((size_t)NPAIR * NH / 4) / 256), 256>>>();

    dim3 g2(ND / 64, NPAIR / 64, NE);         // 16 x 16 x 8
    gemm2_mma<<<g2, 512, G2_SMEM>>>(out);
}

// round 14
// speedup vs baseline: 1.8891x; 1.0964x over previous
#include <cuda_runtime.h>
#include <cuda_fp16.h>
#include <stdint.h>

#define TT    512
#define TOPK  2
#define NE    8
#define NH    2816
#define ND    1024
#define NPAIR 1024

// Scratch
__device__ int d_cnt[NE];
__device__ int d_slot[NE][NPAIR];
__device__ __align__(16) __half d_Gh[(size_t)NPAIR * NH];
__device__ __align__(16) __half d_xh[TT * ND];
__device__ __align__(16) __half d_w1h[(size_t)NE * NH * ND];
__device__ __align__(16) __half d_w3h[(size_t)NE * NH * ND];
__device__ __align__(16) __half d_w2t[(size_t)NE * ND * NH];   // transposed [e][d][h]

// ---------------------------------------------------------------------------
__device__ __forceinline__ uint32_t smem_u32(const void* p) {
    uint32_t a;
    asm("{ .reg .u64 t; cvta.to.shared.u64 t, %1; cvt.u32.u64 %0, t; }" : "=r"(a) : "l"(p));
    return a;
}
__device__ __forceinline__ void ldsm4(uint32_t* r, uint32_t addr) {
    asm volatile("ldmatrix.sync.aligned.m8n8.x4.shared.b16 {%0,%1,%2,%3}, [%4];"
        : "=r"(r[0]), "=r"(r[1]), "=r"(r[2]), "=r"(r[3]) : "r"(addr));
}
__device__ __forceinline__ void mma16816h(float* c, const uint32_t* a, const uint32_t* b) {
    asm volatile("mma.sync.aligned.m16n8k16.row.col.f32.f16.f16.f32 "
        "{%0,%1,%2,%3},{%4,%5,%6,%7},{%8,%9},{%0,%1,%2,%3};"
        : "+f"(c[0]), "+f"(c[1]), "+f"(c[2]), "+f"(c[3])
        : "r"(a[0]), "r"(a[1]), "r"(a[2]), "r"(a[3]), "r"(b[0]), "r"(b[1]));
}
__device__ __forceinline__ void cp16(uint32_t dst, const void* src) {
    asm volatile("cp.async.cg.shared.global [%0], [%1], 16;" :: "r"(dst), "l"(src) : "memory");
}
#define CP_COMMIT() asm volatile("cp.async.commit_group;" ::: "memory")
#define CP_WAIT2()  asm volatile("cp.async.wait_group 2;" ::: "memory")

__device__ __forceinline__ uint32_t pack2h(__half e0, __half e1) {
    return (uint32_t)__half_as_ushort(e0) | ((uint32_t)__half_as_ushort(e1) << 16);
}

// ---------------------------------------------------------------------------
__global__ void route_kernel(const int* __restrict__ eidx) {
    __shared__ int s_cnt[NE];
    int tid = threadIdx.x;
    if (tid < NE) s_cnt[tid] = 0;
    __syncthreads();
    int e = eidx[tid];
    int slot = atomicAdd(&s_cnt[e], 1);
    d_slot[e][slot] = tid;
    __syncthreads();
    if (tid < NE) d_cnt[tid] = s_cnt[tid];
}

__global__ void prep_x(const float* __restrict__ x) {
    size_t i = ((size_t)blockIdx.x * blockDim.x + threadIdx.x) * 4;
    float4 v = *(const float4*)(x + i);
    *(uint2*)(d_xh + i) = make_uint2(pack2h(__float2half_rn(v.x), __float2half_rn(v.y)),
                                     pack2h(__float2half_rn(v.z), __float2half_rn(v.w)));
}

#define W16_BLOCKS 45056
__global__ __launch_bounds__(256) void prep_w(
    const float* __restrict__ w1, const float* __restrict__ w3,
    const float* __restrict__ w2)
{
    __shared__ float sT[64][65];
    int bid = blockIdx.x;
    int tid = threadIdx.x;
    if (bid < W16_BLOCKS) {
        size_t nf4 = (size_t)NE * NH * ND / 4;
        size_t i = (size_t)bid * 256 + tid;
        const float* src = w1; __half* dst = d_w1h;
        if (i >= nf4) { src = w3; dst = d_w3h; i -= nf4; }
        float4 v = ((const float4*)src)[i];
        *(uint2*)(dst + i * 4) =
            make_uint2(pack2h(__float2half_rn(v.x), __float2half_rn(v.y)),
                       pack2h(__float2half_rn(v.z), __float2half_rn(v.w)));
        return;
    }
    int b  = bid - W16_BLOCKS;
    int xd = b & 15;
    int yh = (b >> 4) % 44;
    int e  = b / (16 * 44);
    {
        int row = tid >> 2;
        int seg = (tid & 3) * 16;
        const float* src = w2 + ((size_t)e * NH + yh * 64 + row) * ND + xd * 64 + seg;
        float4 a0 = ((const float4*)src)[0];
        float4 a1 = ((const float4*)src)[1];
        float4 a2 = ((const float4*)src)[2];
        float4 a3 = ((const float4*)src)[3];
        float t[16] = { a0.x,a0.y,a0.z,a0.w, a1.x,a1.y,a1.z,a1.w,
                        a2.x,a2.y,a2.z,a2.w, a3.x,a3.y,a3.z,a3.w };
        #pragma unroll
        for (int i = 0; i < 16; i++) sT[seg + i][row] = t[i];
    }
    __syncthreads();
    {
        int drow = tid >> 2;
        int hseg = (tid & 3) * 16;
        uint32_t o[8];
        #pragma unroll
        for (int i = 0; i < 8; i++)
            o[i] = pack2h(__float2half_rn(sT[drow][hseg + 2 * i]),
                          __float2half_rn(sT[drow][hseg + 2 * i + 1]));
        __half* dst = d_w2t + ((size_t)e * ND + xd * 64 + drow) * NH + yh * 64 + hseg;
        ((uint4*)dst)[0] = make_uint4(o[0], o[1], o[2], o[3]);
        ((uint4*)dst)[1] = make_uint4(o[4], o[5], o[6], o[7]);
    }
}

// ---------------------------------------------------------------------------
// GEMM1 fused: C1,C3[128 pairs x 64 h] = x . w1^T, x . w3^T; epilogue writes
// Gh = silu(C1)*C3 as fp16. K=1024 (16 chunks of 64).
// 4-stage pipeline, SINGLE barrier per chunk (R12-proven shape).
// Stage 32KB: A 16K @0, B1 8K @16384, B3 8K @24576.
// ---------------------------------------------------------------------------
#define G1_STAGE 32768
#define G1_SMEM  (1024 + 4 * G1_STAGE)   // 132096

__global__ __launch_bounds__(512) void gemm1_mma(int dummy)
{
    int e = blockIdx.z;
    int cnt = d_cnt[e];
    int trow0 = blockIdx.y * 128;
    if (trow0 >= cnt) return;
    int col0 = blockIdx.x * 64;

    extern __shared__ char smem[];
    int* s_p   = (int*)smem;
    int* s_tok = (int*)(smem + 512);
    uint32_t sb = smem_u32(smem);

    int tid = threadIdx.x, lane = tid & 31, wid = tid >> 5;
    if (tid < 128) {
        int r = trow0 + tid;
        int p = (r < cnt) ? d_slot[e][r] : d_slot[e][0];
        s_p[tid] = p; s_tok[tid] = p >> 1;
    }
    __syncthreads();

    // A loader: 128 rows x 128B; 4 threads/row, 2 cp16 each
    int arow = tid >> 2, aq = tid & 3;
    uint32_t aswz = (uint32_t)((arow & 7) << 4);
    const __half* xr = d_xh + (size_t)s_tok[arow] * ND + aq * 16;
    uint32_t off0 = (uint32_t)arow * 128 + (((uint32_t)(aq * 32)) ^ aswz);
    uint32_t off1 = (uint32_t)arow * 128 + (((uint32_t)(aq * 32 + 16)) ^ aswz);

    // B loaders: 64 rows x 128B each tensor; 8 threads/row, 1 cp16 per tensor
    int brow = tid >> 3, bq = tid & 7;
    const __half* w1r = d_w1h + ((size_t)e * NH + col0 + brow) * ND + bq * 8;
    const __half* w3r = d_w3h + ((size_t)e * NH + col0 + brow) * ND + bq * 8;
    uint32_t boff = (uint32_t)brow * 128 +
        (((uint32_t)(bq * 16)) ^ (uint32_t)((brow & 7) << 4));

    float acc1[2][2][4], acc3[2][2][4];
    #pragma unroll
    for (int a = 0; a < 2; a++)
        #pragma unroll
        for (int b = 0; b < 2; b++)
            #pragma unroll
            for (int c = 0; c < 4; c++) { acc1[a][b][c] = 0.0f; acc3[a][b][c] = 0.0f; }

    int wm = wid & 3, wn = wid >> 2;   // 4 x 32 pairs, 4 x 16 h

    #define G1_ISSUE(KC, ST) do { \
        uint32_t base = sb + 1024 + (ST) * G1_STAGE; \
        const char* sa = (const char*)(xr + (KC) * 64); \
        cp16(base + off0, sa); \
        cp16(base + off1, sa + 16); \
        cp16(base + 16384 + boff, (const char*)(w1r + (KC) * 64)); \
        cp16(base + 24576 + boff, (const char*)(w3r + (KC) * 64)); \
    } while (0)

    G1_ISSUE(0, 0); CP_COMMIT();
    G1_ISSUE(1, 1); CP_COMMIT();
    G1_ISSUE(2, 2); CP_COMMIT();

    #pragma unroll 1
    for (int kc = 0; kc < 16; kc++) {
        CP_WAIT2();
        __syncthreads();
        if (kc + 3 < 16) G1_ISSUE(kc + 3, (kc + 3) & 3);
        CP_COMMIT();

        uint32_t uA  = sb + 1024 + (kc & 3) * G1_STAGE;
        uint32_t uB1 = uA + 16384;
        uint32_t uB3 = uA + 24576;
        #pragma unroll
        for (int ks = 0; ks < 4; ks++) {
            uint32_t Ah[2][4], B1h[4], B3h[4];
            int kb = ks * 32;
            #pragma unroll
            for (int mi = 0; mi < 2; mi++) {
                int row = wm * 32 + mi * 16 + (lane & 15);
                uint32_t bb = (uint32_t)(kb + ((lane >> 4) << 4));
                uint32_t off = (uint32_t)row * 128 + (bb ^ (uint32_t)((row & 7) << 4));
                ldsm4(Ah[mi], uA + off);
            }
            {
                int row = wn * 16 + (lane & 7) + (((lane >> 4) & 1) << 3);
                uint32_t bb = (uint32_t)(kb + (((lane >> 3) & 1) << 4));
                uint32_t off = (uint32_t)row * 128 + (bb ^ (uint32_t)((row & 7) << 4));
                ldsm4(B1h, uB1 + off);
                ldsm4(B3h, uB3 + off);
            }
            #pragma unroll
            for (int mi = 0; mi < 2; mi++) {
                mma16816h(acc1[mi][0], Ah[mi], &B1h[0]);
                mma16816h(acc1[mi][1], Ah[mi], &B1h[2]);
                mma16816h(acc3[mi][0], Ah[mi], &B3h[0]);
                mma16816h(acc3[mi][1], Ah[mi], &B3h[2]);
            }
        }
    }
    #undef G1_ISSUE

    // Epilogue: Gh = silu(c1) * c3, fp16, written once per (pair, h)
    int cntLoc = cnt - trow0; if (cntLoc > 128) cntLoc = 128;
    #pragma unroll
    for (int mi = 0; mi < 2; mi++) {
        int r0 = wm * 32 + mi * 16 + (lane >> 2);
        int r1 = r0 + 8;
        #pragma unroll
        for (int ni = 0; ni < 2; ni++) {
            int col = col0 + wn * 16 + ni * 8 + (lane & 3) * 2;
            if (r0 < cntLoc) {
                float a = acc1[mi][ni][0], b = acc1[mi][ni][1];
                float g0 = __fdividef(a, 1.0f + __expf(-a)) * acc3[mi][ni][0];
                float g1 = __fdividef(b, 1.0f + __expf(-b)) * acc3[mi][ni][1];
                *(uint32_t*)&d_Gh[(size_t)s_p[r0] * NH + col] =
                    pack2h(__float2half_rn(g0), __float2half_rn(g1));
            }
            if (r1 < cntLoc) {
                float a = acc1[mi][ni][2], b = acc1[mi][ni][3];
                float g0 = __fdividef(a, 1.0f + __expf(-a)) * acc3[mi][ni][2];
                float g1 = __fdividef(b, 1.0f + __expf(-b)) * acc3[mi][ni][3];
                *(uint32_t*)&d_Gh[(size_t)s_p[r1] * NH + col] =
                    pack2h(__float2half_rn(g0), __float2half_rn(g1));
            }
        }
    }
}

// ---------------------------------------------------------------------------
// GEMM2: C[64 pairs x 64 d] = G . w2t, K=2816 (44 chunks of 64)
// 4-stage pipeline (stage 16KB: A 8K, B 8K), single barrier, 2 CTAs/SM.
// ---------------------------------------------------------------------------
#define G2_STAGE 16384
#define G2_SMEM  (1024 + 4 * G2_STAGE)   // 66560

__global__ __launch_bounds__(512, 2) void gemm2_mma(float* __restrict__ out)
{
    int e = blockIdx.z;
    int cnt = d_cnt[e];
    int trow0 = blockIdx.y * 64;
    if (trow0 >= cnt) return;
    int col0 = blockIdx.x * 64;

    extern __shared__ char smem[];
    int* s_p = (int*)smem;
    uint32_t sb = smem_u32(smem);

    int tid = threadIdx.x, lane = tid & 31, wid = tid >> 5;
    if (tid < 64) {
        int r = trow0 + tid;
        s_p[tid] = (r < cnt) ? d_slot[e][r] : d_slot[e][0];
    }
    __syncthreads();

    int lrow = tid >> 3, lq = tid & 7;
    uint32_t loff = (uint32_t)lrow * 128 +
        (((uint32_t)(lq * 16)) ^ (uint32_t)((lrow & 7) << 4));
    const __half* gr = d_Gh + (size_t)s_p[lrow] * NH + lq * 8;
    const __half* br = d_w2t + ((size_t)e * ND + col0 + lrow) * NH + lq * 8;

    float acc[2][4];
    #pragma unroll
    for (int b = 0; b < 2; b++)
        #pragma unroll
        for (int c = 0; c < 4; c++) acc[b][c] = 0.0f;

    int wm = wid & 3, wn = wid >> 2;

    #define G2_ISSUE(KC, ST) do { \
        uint32_t base = sb + 1024 + (ST) * G2_STAGE; \
        cp16(base + loff, (const char*)(gr + (KC) * 64)); \
        cp16(base + 8192 + loff, (const char*)(br + (KC) * 64)); \
    } while (0)

    G2_ISSUE(0, 0); CP_COMMIT();
    G2_ISSUE(1, 1); CP_COMMIT();
    G2_ISSUE(2, 2); CP_COMMIT();

    #pragma unroll 1
    for (int kc = 0; kc < 44; kc++) {
        CP_WAIT2();
        __syncthreads();
        if (kc + 3 < 44) G2_ISSUE(kc + 3, (kc + 3) & 3);
        CP_COMMIT();

        uint32_t uAH = sb + 1024 + (kc & 3) * G2_STAGE;
        uint32_t uBH = uAH + 8192;
        #pragma unroll
        for (int ks = 0; ks < 4; ks++) {
            uint32_t Ah[4], Bh[4];
            int kb = ks * 32;
            {
                int row = wm * 16 + (lane & 15);
                uint32_t bb = (uint32_t)(kb + ((lane >> 4) << 4));
                uint32_t off = (uint32_t)row * 128 + (bb ^ (uint32_t)((row & 7) << 4));
                ldsm4(Ah, uAH + off);
            }
            {
                int row = wn * 16 + (lane & 7) + (((lane >> 4) & 1) << 3);
                uint32_t bb = (uint32_t)(kb + (((lane >> 3) & 1) << 4));
                uint32_t off = (uint32_t)row * 128 + (bb ^ (uint32_t)((row & 7) << 4));
                ldsm4(Bh, uBH + off);
            }
            mma16816h(acc[0], Ah, &Bh[0]);
            mma16816h(acc[1], Ah, &Bh[2]);
        }
    }
    #undef G2_ISSUE

    int cntLoc = cnt - trow0; if (cntLoc > 64) cntLoc = 64;
    {
        int r0 = wm * 16 + (lane >> 2);
        int r1 = r0 + 8;
        #pragma unroll
        for (int ni = 0; ni < 2; ni++) {
            int col = col0 + wn * 16 + ni * 8 + (lane & 3) * 2;
            if (r0 < cntLoc)
                *(float2*)&out[(size_t)s_p[r0] * ND + col] =
                    make_float2(acc[ni][0], acc[ni][1]);
            if (r1 < cntLoc)
                *(float2*)&out[(size_t)s_p[r1] * ND + col] =
                    make_float2(acc[ni][2], acc[ni][3]);
        }
    }
}

// ---------------------------------------------------------------------------
extern "C" void kernel_launch(void* const* d_in, const int* in_sizes, int n_in,
                              void* d_out, int out_size) {
    const float* x    = (const float*)d_in[0];
    const int*   eidx = (const int*)d_in[1];   // int32 (JAX default int)
    const float* w1   = (const float*)d_in[2];
    const float* w2   = (const float*)d_in[3];
    const float* w3   = (const float*)d_in[4];
    float*       out  = (float*)d_out;

    static bool attr_done = false;
    if (!attr_done) {
        cudaFuncSetAttribute(gemm1_mma, cudaFuncAttributeMaxDynamicSharedMemorySize, G1_SMEM);
        cudaFuncSetAttribute(gemm2_mma, cudaFuncAttributeMaxDynamicSharedMemorySize, G2_SMEM);
        attr_done = true;
    }

    route_kernel<<<1, NPAIR>>>(eidx);
    prep_x<<<(TT * ND / 4) / 256, 256>>>(x);
    prep_w<<<W16_BLOCKS + 16 * 44 * NE, 256>>>(w1, w3, w2);

    dim3 g1(NH / 64, NPAIR / 128, NE);   // 44 x 8 x 8
    gemm1_mma<<<g1, 512, G1_SMEM>>>(0);

    dim3 g2(ND / 64, NPAIR / 64, NE);    // 16 x 16 x 8
    gemm2_mma<<<g2, 512, G2_SMEM>>>(out);
}